// round 2
// baseline (speedup 1.0000x reference)
#include <cuda_runtime.h>
#include <cuda_bf16.h>
#include <math.h>

#define NN 50000
#define NE 800000
#define C  128

// ---------------- device scratch (static allocation, allowed) ----------------
static __device__ float g_h1[(size_t)NE * C];    // edge hidden (stage1 out / node t1 reuse)
static __device__ float g_hneigh[(size_t)NN * C];
static __device__ float g_xsum[NN * 3];
static __device__ float g_deg[NN];
static __device__ float g_red[16];

__device__ __forceinline__ float silu_f(float v) {
    return v / (1.0f + __expf(-v));
}

// 64-row x 128-col tile GEMM microkernel: 256 threads, thread (tx,ty) owns
// rows e0=4*ty..+3, cols j0=8*tx..+7. A is [64][KK] row-major in smem,
// W is [KK][128] row-major in smem.
template <int KK>
__device__ __forceinline__ void gemm_tile(const float* __restrict__ sA,
                                          const float* __restrict__ sW,
                                          float (&acc)[4][8], int e0, int j0) {
#pragma unroll 4
    for (int k = 0; k < KK; ++k) {
        float a0 = sA[(e0 + 0) * KK + k];
        float a1 = sA[(e0 + 1) * KK + k];
        float a2 = sA[(e0 + 2) * KK + k];
        float a3 = sA[(e0 + 3) * KK + k];
        float4 w0 = *(const float4*)&sW[k * C + j0];
        float4 w1 = *(const float4*)&sW[k * C + j0 + 4];
        float w[8] = {w0.x, w0.y, w0.z, w0.w, w1.x, w1.y, w1.z, w1.w};
#pragma unroll
        for (int jj = 0; jj < 8; ++jj) {
            acc[0][jj] = fmaf(a0, w[jj], acc[0][jj]);
            acc[1][jj] = fmaf(a1, w[jj], acc[1][jj]);
            acc[2][jj] = fmaf(a2, w[jj], acc[2][jj]);
            acc[3][jj] = fmaf(a3, w[jj], acc[3][jj]);
        }
    }
}

// ---------------- k_init: zero all accumulators ----------------
__global__ void k_init() {
    const long NC = (long)NN * C, N3 = NN * 3;
    const long TOT = NC + N3 + NN + 16;
    long stride = (long)gridDim.x * blockDim.x;
    for (long i = (long)blockIdx.x * blockDim.x + threadIdx.x; i < TOT; i += stride) {
        if (i < NC) g_hneigh[i] = 0.f;
        else if (i < NC + N3) g_xsum[i - NC] = 0.f;
        else if (i < NC + N3 + NN) g_deg[i - NC - N3] = 0.f;
        else g_red[i - NC - N3 - NN] = 0.f;
    }
}

// ---------------- k_deg: degree histogram ----------------
__global__ void k_deg(const int* __restrict__ dst) {
    int stride = gridDim.x * blockDim.x;
    for (int e = blockIdx.x * blockDim.x + threadIdx.x; e < NE; e += stride)
        atomicAdd(&g_deg[dst[e]], 1.0f);
}

// ---------------- k_edge1: h1 = silu([nf_s|nf_d|radial] @ W1 + b1) ----------------
__global__ void __launch_bounds__(256, 1)
k_edge1(const float* __restrict__ nf, const float* __restrict__ coord,
        const int* __restrict__ src, const int* __restrict__ dst,
        const float* __restrict__ W1, const float* __restrict__ b1) {
    extern __shared__ char smraw[];
    float* sW   = (float*)smraw;        // 256*128
    float* sA   = sW + 32768;           // 64*256
    float* sB   = sA + 16384;           // 128
    float* sWr  = sB + 128;             // 128 (radial row of W1)
    float* sRad = sWr + 128;            // 64
    int*   sSrc = (int*)(sRad + 64);    // 64
    int*   sDst = sSrc + 64;            // 64

    int tid = threadIdx.x;
    for (int i = tid; i < 32768; i += 256) sW[i] = W1[i];
    if (tid < 128) { sB[tid] = b1[tid]; sWr[tid] = W1[32768 + tid]; }
    __syncthreads();

    int tx = tid & 15, ty = tid >> 4;
    int e0 = ty * 4, j0 = tx * 8;
    float bw[8], rw[8];
#pragma unroll
    for (int jj = 0; jj < 8; ++jj) { bw[jj] = sB[j0 + jj]; rw[jj] = sWr[j0 + jj]; }

    const int ntiles = NE / 64;
    for (int tile = blockIdx.x; tile < ntiles; tile += gridDim.x) {
        int be = tile * 64;
        if (tid < 64) {
            int e = be + tid;
            int s = src[e], d = dst[e];
            sSrc[tid] = s; sDst[tid] = d;
            float dx = coord[s * 3 + 0] - coord[d * 3 + 0];
            float dy = coord[s * 3 + 1] - coord[d * 3 + 1];
            float dz = coord[s * 3 + 2] - coord[d * 3 + 2];
            sRad[tid] = dx * dx + dy * dy + dz * dz;
        }
        __syncthreads();
#pragma unroll 2
        for (int it = 0; it < 64; ++it) {
            int s = sSrc[it], d = sDst[it];
            int c = tid;
            float v = (c < 128) ? nf[s * 128 + c] : nf[d * 128 + (c - 128)];
            sA[it * 256 + c] = v;
        }
        __syncthreads();

        float acc[4][8];
#pragma unroll
        for (int ee = 0; ee < 4; ++ee) {
            float r = sRad[e0 + ee];
#pragma unroll
            for (int jj = 0; jj < 8; ++jj) acc[ee][jj] = fmaf(r, rw[jj], bw[jj]);
        }
        gemm_tile<256>(sA, sW, acc, e0, j0);

#pragma unroll
        for (int ee = 0; ee < 4; ++ee) {
            float4 o0, o1;
            o0.x = silu_f(acc[ee][0]); o0.y = silu_f(acc[ee][1]);
            o0.z = silu_f(acc[ee][2]); o0.w = silu_f(acc[ee][3]);
            o1.x = silu_f(acc[ee][4]); o1.y = silu_f(acc[ee][5]);
            o1.z = silu_f(acc[ee][6]); o1.w = silu_f(acc[ee][7]);
            size_t base = (size_t)(be + e0 + ee) * C + j0;
            *(float4*)&g_h1[base]     = o0;
            *(float4*)&g_h1[base + 4] = o1;
        }
        __syncthreads();
    }
}

// ---------------- k_edge2: msg_h = silu(h1@W2+b2); scatter; coord path ----------------
__global__ void __launch_bounds__(256, 1)
k_edge2(const float* __restrict__ coord,
        const int* __restrict__ src, const int* __restrict__ dst,
        const float* __restrict__ W2, const float* __restrict__ b2,
        const float* __restrict__ W5, const float* __restrict__ b5,
        const float* __restrict__ W6) {
    extern __shared__ char smraw[];
    float* sW2 = (float*)smraw;       // 128*128
    float* sW5 = sW2 + 16384;         // 128*128
    float* sH1 = sW5 + 16384;         // 64*128
    float* sH2 = sH1 + 8192;          // 64*128
    float* sB2 = sH2 + 8192;          // 128
    float* sB5 = sB2 + 128;           // 128
    float* sW6 = sB5 + 128;           // 128
    int*   sSrc = (int*)(sW6 + 128);  // 64
    int*   sDst = sSrc + 64;          // 64

    int tid = threadIdx.x;
    for (int i = tid; i < 16384; i += 256) { sW2[i] = W2[i]; sW5[i] = W5[i]; }
    if (tid < 128) { sB2[tid] = b2[tid]; sB5[tid] = b5[tid]; sW6[tid] = W6[tid]; }
    __syncthreads();

    int tx = tid & 15, ty = tid >> 4;
    int e0 = ty * 4, j0 = tx * 8;
    float b2r[8], b5r[8], w6r[8];
#pragma unroll
    for (int jj = 0; jj < 8; ++jj) {
        b2r[jj] = sB2[j0 + jj]; b5r[jj] = sB5[j0 + jj]; w6r[jj] = sW6[j0 + jj];
    }

    const int ntiles = NE / 64;
    for (int tile = blockIdx.x; tile < ntiles; tile += gridDim.x) {
        int be = tile * 64;
        if (tid < 64) { sSrc[tid] = src[be + tid]; sDst[tid] = dst[be + tid]; }
        for (int i = tid; i < 8192; i += 256) sH1[i] = g_h1[(size_t)be * C + i];
        __syncthreads();

        // GEMM1: h2 = silu(h1@W2 + b2)
        float acc[4][8];
#pragma unroll
        for (int ee = 0; ee < 4; ++ee)
#pragma unroll
            for (int jj = 0; jj < 8; ++jj) acc[ee][jj] = b2r[jj];
        gemm_tile<128>(sH1, sW2, acc, e0, j0);

        float h2v[4][8];
#pragma unroll
        for (int ee = 0; ee < 4; ++ee) {
            int d = sDst[e0 + ee];
            float* hn = &g_hneigh[(size_t)d * C + j0];
#pragma unroll
            for (int jj = 0; jj < 8; ++jj) {
                float v = silu_f(acc[ee][jj]);
                h2v[ee][jj] = v;
                sH2[(e0 + ee) * C + j0 + jj] = v;
                atomicAdd(&hn[jj], v);
            }
        }
        __syncthreads();

        // GEMM2: h3 = silu(h2@W5 + b5); cw = h3 . W6
        float acc2[4][8];
#pragma unroll
        for (int ee = 0; ee < 4; ++ee)
#pragma unroll
            for (int jj = 0; jj < 8; ++jj) acc2[ee][jj] = b5r[jj];
        gemm_tile<128>(sH2, sW5, acc2, e0, j0);

        float cw[4];
#pragma unroll
        for (int ee = 0; ee < 4; ++ee) {
            float c = 0.f;
#pragma unroll
            for (int jj = 0; jj < 8; ++jj) c = fmaf(silu_f(acc2[ee][jj]), w6r[jj], c);
#pragma unroll
            for (int off = 8; off >= 1; off >>= 1)
                c += __shfl_xor_sync(0xffffffffu, c, off, 16);
            cw[ee] = c;
        }
        if (tx == 0) {
#pragma unroll
            for (int ee = 0; ee < 4; ++ee) {
                int s = sSrc[e0 + ee], d = sDst[e0 + ee];
                float dx = coord[s * 3 + 0] - coord[d * 3 + 0];
                float dy = coord[s * 3 + 1] - coord[d * 3 + 1];
                float dz = coord[s * 3 + 2] - coord[d * 3 + 2];
                float r  = dx * dx + dy * dy + dz * dz;
                float inv = 1.0f / (sqrtf(r + 1e-6f) + 1e-6f);
                float cws = cw[ee] * inv;
                atomicAdd(&g_xsum[d * 3 + 0], cws * dx);
                atomicAdd(&g_xsum[d * 3 + 1], cws * dy);
                atomicAdd(&g_xsum[d * 3 + 2], cws * dz);
            }
        }
        __syncthreads();
    }
}

// ---------------- k_node1: t1 = silu([nf|h_neigh] @ W3 + b3) -> g_h1 ----------------
__global__ void __launch_bounds__(256, 1)
k_node1(const float* __restrict__ nf, const float* __restrict__ W3,
        const float* __restrict__ b3) {
    extern __shared__ char smraw[];
    float* sW = (float*)smraw;   // 256*128
    float* sA = sW + 32768;      // 64*256
    float* sB = sA + 16384;      // 128

    int tid = threadIdx.x;
    for (int i = tid; i < 32768; i += 256) sW[i] = W3[i];
    if (tid < 128) sB[tid] = b3[tid];
    __syncthreads();

    int tx = tid & 15, ty = tid >> 4;
    int e0 = ty * 4, j0 = tx * 8;
    float bw[8];
#pragma unroll
    for (int jj = 0; jj < 8; ++jj) bw[jj] = sB[j0 + jj];

    const int ntiles = (NN + 63) / 64;
    for (int tile = blockIdx.x; tile < ntiles; tile += gridDim.x) {
        int bn = tile * 64;
        for (int i = tid; i < 16384; i += 256) {
            int row = i >> 8, c = i & 255;
            int n = bn + row;
            float v = 0.f;
            if (n < NN)
                v = (c < 128) ? nf[(size_t)n * 128 + c]
                              : g_hneigh[(size_t)n * 128 + (c - 128)];
            sA[i] = v;
        }
        __syncthreads();

        float acc[4][8];
#pragma unroll
        for (int ee = 0; ee < 4; ++ee)
#pragma unroll
            for (int jj = 0; jj < 8; ++jj) acc[ee][jj] = bw[jj];
        gemm_tile<256>(sA, sW, acc, e0, j0);

#pragma unroll
        for (int ee = 0; ee < 4; ++ee) {
            int n = bn + e0 + ee;
            if (n < NN) {
                float4 o0, o1;
                o0.x = silu_f(acc[ee][0]); o0.y = silu_f(acc[ee][1]);
                o0.z = silu_f(acc[ee][2]); o0.w = silu_f(acc[ee][3]);
                o1.x = silu_f(acc[ee][4]); o1.y = silu_f(acc[ee][5]);
                o1.z = silu_f(acc[ee][6]); o1.w = silu_f(acc[ee][7]);
                size_t base = (size_t)n * C + j0;
                *(float4*)&g_h1[base]     = o0;
                *(float4*)&g_h1[base + 4] = o1;
            }
        }
        __syncthreads();
    }
}

// ---------------- k_node2: h = t1 @ W4 + b4 -> out ----------------
__global__ void __launch_bounds__(256, 1)
k_node2(const float* __restrict__ W4, const float* __restrict__ b4,
        float* __restrict__ outh) {
    extern __shared__ char smraw[];
    float* sW = (float*)smraw;   // 128*128
    float* sT = sW + 16384;      // 64*128
    float* sB = sT + 8192;       // 128

    int tid = threadIdx.x;
    for (int i = tid; i < 16384; i += 256) sW[i] = W4[i];
    if (tid < 128) sB[tid] = b4[tid];
    __syncthreads();

    int tx = tid & 15, ty = tid >> 4;
    int e0 = ty * 4, j0 = tx * 8;
    float bw[8];
#pragma unroll
    for (int jj = 0; jj < 8; ++jj) bw[jj] = sB[j0 + jj];

    const int ntiles = (NN + 63) / 64;
    for (int tile = blockIdx.x; tile < ntiles; tile += gridDim.x) {
        int bn = tile * 64;
        for (int i = tid; i < 8192; i += 256) {
            int n = bn + (i >> 7);
            sT[i] = (n < NN) ? g_h1[(size_t)bn * C + i] : 0.f;
        }
        __syncthreads();

        float acc[4][8];
#pragma unroll
        for (int ee = 0; ee < 4; ++ee)
#pragma unroll
            for (int jj = 0; jj < 8; ++jj) acc[ee][jj] = bw[jj];
        gemm_tile<128>(sT, sW, acc, e0, j0);

#pragma unroll
        for (int ee = 0; ee < 4; ++ee) {
            int n = bn + e0 + ee;
            if (n < NN) {
                float4 o0 = make_float4(acc[ee][0], acc[ee][1], acc[ee][2], acc[ee][3]);
                float4 o1 = make_float4(acc[ee][4], acc[ee][5], acc[ee][6], acc[ee][7]);
                size_t base = (size_t)n * C + j0;
                *(float4*)&outh[base]     = o0;
                *(float4*)&outh[base + 4] = o1;
            }
        }
        __syncthreads();
    }
}

// ---------------- k_x: x = coord + xsum/deg ; accumulate mean/var sums ----------------
__global__ void k_x(const float* __restrict__ coord, float* __restrict__ outx) {
    __shared__ float sred[6];
    int tid = threadIdx.x;
    if (tid < 6) sred[tid] = 0.f;
    __syncthreads();
    float ls[6] = {0.f, 0.f, 0.f, 0.f, 0.f, 0.f};
    int stride = gridDim.x * blockDim.x;
    for (int n = blockIdx.x * blockDim.x + tid; n < NN; n += stride) {
        float deg = fmaxf(g_deg[n], 1.0f);
        float invd = 1.0f / deg;
#pragma unroll
        for (int d = 0; d < 3; ++d) {
            float x = coord[n * 3 + d] + g_xsum[n * 3 + d] * invd;
            outx[n * 3 + d] = x;
            ls[d] += x;
            ls[3 + d] += x * x;
        }
    }
#pragma unroll
    for (int k = 0; k < 6; ++k) atomicAdd(&sred[k], ls[k]);
    __syncthreads();
    if (tid < 6) atomicAdd(&g_red[tid], sred[tid]);
}

// ---------------- k_fin: compute mean / inv-std ----------------
__global__ void k_fin() {
    int t = threadIdx.x;
    if (t < 3) {
        float mean = g_red[t] / (float)NN;
        float m2   = g_red[3 + t] / (float)NN;
        float var  = m2 - mean * mean;
        g_red[8 + t]  = mean;
        g_red[11 + t] = 1.0f / (sqrtf(var + 1e-6f) + 1e-6f);
    }
}

// ---------------- k_norm: in-place normalize x ----------------
__global__ void k_norm(float* __restrict__ outx) {
    int stride = gridDim.x * blockDim.x;
    for (int i = blockIdx.x * blockDim.x + threadIdx.x; i < NN * 3; i += stride) {
        int d = i % 3;
        outx[i] = (outx[i] - g_red[8 + d]) * g_red[11 + d];
    }
}

// ---------------- launch ----------------
extern "C" void kernel_launch(void* const* d_in, const int* in_sizes, int n_in,
                              void* d_out, int out_size) {
    const float* nf    = (const float*)d_in[0];
    const float* coord = (const float*)d_in[1];
    const int*   src   = (const int*)d_in[2];
    const int*   dst   = (const int*)d_in[3];
    const float* W1 = (const float*)d_in[4];
    const float* b1 = (const float*)d_in[5];
    const float* W2 = (const float*)d_in[6];
    const float* b2 = (const float*)d_in[7];
    const float* W3 = (const float*)d_in[8];
    const float* b3 = (const float*)d_in[9];
    const float* W4 = (const float*)d_in[10];
    const float* b4 = (const float*)d_in[11];
    const float* W5 = (const float*)d_in[12];
    const float* b5 = (const float*)d_in[13];
    const float* W6 = (const float*)d_in[14];

    float* outh = (float*)d_out;
    float* outx = outh + (size_t)NN * C;

    const int SM_E1 = (32768 + 16384 + 128 + 128 + 64) * 4 + 128 * 4;
    const int SM_E2 = (16384 + 16384 + 8192 + 8192 + 128 + 128 + 128) * 4 + 128 * 4;
    const int SM_N1 = (32768 + 16384 + 128) * 4;
    const int SM_N2 = (16384 + 8192 + 128) * 4;

    cudaFuncSetAttribute(k_edge1, cudaFuncAttributeMaxDynamicSharedMemorySize, SM_E1);
    cudaFuncSetAttribute(k_edge2, cudaFuncAttributeMaxDynamicSharedMemorySize, SM_E2);
    cudaFuncSetAttribute(k_node1, cudaFuncAttributeMaxDynamicSharedMemorySize, SM_N1);
    cudaFuncSetAttribute(k_node2, cudaFuncAttributeMaxDynamicSharedMemorySize, SM_N2);

    k_init<<<2048, 256>>>();
    k_deg<<<512, 256>>>(dst);
    k_edge1<<<148, 256, SM_E1>>>(nf, coord, src, dst, W1, b1);
    k_edge2<<<148, 256, SM_E2>>>(coord, src, dst, W2, b2, W5, b5, W6);
    k_node1<<<148, 256, SM_N1>>>(nf, W3, b3);
    k_node2<<<148, 256, SM_N2>>>(W4, b4, outh);
    k_x<<<160, 256>>>(coord, outx);
    k_fin<<<1, 32>>>();
    k_norm<<<160, 256>>>(outx);
}

// round 3
// speedup vs baseline: 3.3456x; 3.3456x over previous
#include <cuda_runtime.h>
#include <cuda_bf16.h>
#include <math.h>

#define NN 50000
#define NE 800000
#define C  128

// ---------------- device scratch ----------------
static __device__ float g_h1[(size_t)NE * C];    // edge hidden / node t1 reuse
static __device__ float g_hneigh[(size_t)NN * C];
static __device__ float g_xsum[NN * 3];
static __device__ float g_deg[NN];
static __device__ float g_red[16];

__device__ __forceinline__ float silu_f(float v) {
    return v / (1.0f + __expf(-v));
}

// round fp32 -> tf32 (rna), value kept in fp32 container
__device__ __forceinline__ float tf32f(float x) {
    unsigned u;
    asm("cvt.rna.tf32.f32 %0, %1;" : "=r"(u) : "f"(x));
    return __uint_as_float(u);
}

__device__ __forceinline__ void mma8(float* d, const unsigned* a, unsigned b0, unsigned b1) {
    asm volatile(
        "mma.sync.aligned.m16n8k8.row.col.f32.tf32.tf32.f32 "
        "{%0,%1,%2,%3}, {%4,%5,%6,%7}, {%8,%9}, {%0,%1,%2,%3};"
        : "+f"(d[0]), "+f"(d[1]), "+f"(d[2]), "+f"(d[3])
        : "r"(a[0]), "r"(a[1]), "r"(a[2]), "r"(a[3]), "r"(b0), "r"(b1));
}

// Warp-tile GEMM: CTA tile 128 rows x 128 cols, 8 warps as 4(row) x 2(col),
// each warp 32x64. sA row-major [128][SA], sW row-major [K][SW].
// SA % 32 must be in {4,12,20,28}; SW % 32 == 8 for conflict-free frags.
template<int SA, int SW, bool CVT>
__device__ __forceinline__ void gemm_mma(const float* __restrict__ sA,
                                         const float* __restrict__ sW,
                                         int kchunks, float (&acc)[2][8][4],
                                         int wr, int wc, int lane) {
    const int g = lane >> 2, t = lane & 3;
    const float* a0p = sA + (wr * 32 + g) * SA + t;
    const float* bB  = sW + t * SW + wc * 64 + g;
#pragma unroll 4
    for (int kc = 0; kc < kchunks; ++kc) {
        unsigned A0[4], A1[4];
        const float* ap = a0p + kc * 8;
        const float* ap1 = ap + 16 * SA;
        if (CVT) {
            A0[0] = __float_as_uint(tf32f(ap[0]));
            A0[1] = __float_as_uint(tf32f(ap[8 * SA]));
            A0[2] = __float_as_uint(tf32f(ap[4]));
            A0[3] = __float_as_uint(tf32f(ap[8 * SA + 4]));
            A1[0] = __float_as_uint(tf32f(ap1[0]));
            A1[1] = __float_as_uint(tf32f(ap1[8 * SA]));
            A1[2] = __float_as_uint(tf32f(ap1[4]));
            A1[3] = __float_as_uint(tf32f(ap1[8 * SA + 4]));
        } else {
            A0[0] = __float_as_uint(ap[0]);
            A0[1] = __float_as_uint(ap[8 * SA]);
            A0[2] = __float_as_uint(ap[4]);
            A0[3] = __float_as_uint(ap[8 * SA + 4]);
            A1[0] = __float_as_uint(ap1[0]);
            A1[1] = __float_as_uint(ap1[8 * SA]);
            A1[2] = __float_as_uint(ap1[4]);
            A1[3] = __float_as_uint(ap1[8 * SA + 4]);
        }
        const float* bp = bB + kc * 8 * SW;
#pragma unroll
        for (int ni = 0; ni < 8; ++ni) {
            unsigned b0 = __float_as_uint(bp[ni * 8]);
            unsigned b1 = __float_as_uint(bp[4 * SW + ni * 8]);
            mma8(acc[0][ni], A0, b0, b1);
            mma8(acc[1][ni], A1, b0, b1);
        }
    }
}

// ---------------- k_init ----------------
__global__ void k_init() {
    const long NC = (long)NN * C, N3 = NN * 3;
    const long TOT = NC + N3 + NN + 16;
    long stride = (long)gridDim.x * blockDim.x;
    for (long i = (long)blockIdx.x * blockDim.x + threadIdx.x; i < TOT; i += stride) {
        if (i < NC) g_hneigh[i] = 0.f;
        else if (i < NC + N3) g_xsum[i - NC] = 0.f;
        else if (i < NC + N3 + NN) g_deg[i - NC - N3] = 0.f;
        else g_red[i - NC - N3 - NN] = 0.f;
    }
}

// ---------------- k_deg ----------------
__global__ void k_deg(const int* __restrict__ dst) {
    int stride = gridDim.x * blockDim.x;
    for (int e = blockIdx.x * blockDim.x + threadIdx.x; e < NE; e += stride)
        atomicAdd(&g_deg[dst[e]], 1.0f);
}

// ---------------- k_edge1: h1 = silu([nf_s|nf_d|radial] @ W1 + b1) -> g_h1 ----------------
// smem: sWa[128][136] | sWb[136][136] | sA[128][140] | sB[128] | sRad[128] | idx
__global__ void __launch_bounds__(256, 1)
k_edge1(const float* __restrict__ nf, const float* __restrict__ coord,
        const int* __restrict__ src, const int* __restrict__ dst,
        const float* __restrict__ W1, const float* __restrict__ b1) {
    extern __shared__ float sm[];
    float* sWa = sm;                       // 128*136
    float* sWb = sWa + 128 * 136;          // 136*136
    float* sA  = sWb + 136 * 136;          // 128*140
    float* sB  = sA + 128 * 140;           // 128
    float* sRad = sB + 128;                // 128
    int* sSrc = (int*)(sRad + 128);        // 128
    int* sDst = sSrc + 128;                // 128

    const int tid = threadIdx.x, lane = tid & 31, wid = tid >> 5;
    const int wr = wid & 3, wc = wid >> 2;

    for (int i = tid; i < 128 * 128; i += 256) {
        int k = i >> 7, n = i & 127;
        sWa[k * 136 + n] = tf32f(W1[i]);
        sWb[k * 136 + n] = tf32f(W1[128 * 128 + i]);
    }
    for (int i = tid; i < 8 * 128; i += 256) {
        int k = 128 + (i >> 7), n = i & 127;
        sWb[k * 136 + n] = (k == 128) ? tf32f(W1[256 * 128 + n]) : 0.f;
    }
    if (tid < 128) sB[tid] = b1[tid];
    __syncthreads();

    float blo[8], bhi[8];
    {
        int c = wc * 64 + 2 * (lane & 3);
#pragma unroll
        for (int ni = 0; ni < 8; ++ni) { blo[ni] = sB[c + ni * 8]; bhi[ni] = sB[c + ni * 8 + 1]; }
    }

    const int ntiles = NE / 128;
    for (int tile = blockIdx.x; tile < ntiles; tile += gridDim.x) {
        const int be = tile * 128;
        if (tid < 128) {
            int e = be + tid;
            int s = src[e], d = dst[e];
            sSrc[tid] = s; sDst[tid] = d;
            float dx = coord[s * 3 + 0] - coord[d * 3 + 0];
            float dy = coord[s * 3 + 1] - coord[d * 3 + 1];
            float dz = coord[s * 3 + 2] - coord[d * 3 + 2];
            sRad[tid] = dx * dx + dy * dy + dz * dz;
        }
        __syncthreads();
        // chunk A: nf[src]
        for (int i = tid; i < 128 * 32; i += 256) {
            int row = i >> 5, c4 = (i & 31) * 4;
            const float4 v = *(const float4*)&nf[(size_t)sSrc[row] * 128 + c4];
            float* p = &sA[row * 140 + c4];
            p[0] = tf32f(v.x); p[1] = tf32f(v.y); p[2] = tf32f(v.z); p[3] = tf32f(v.w);
        }
        __syncthreads();

        float acc[2][8][4];
#pragma unroll
        for (int mi = 0; mi < 2; ++mi)
#pragma unroll
            for (int ni = 0; ni < 8; ++ni) {
                acc[mi][ni][0] = blo[ni]; acc[mi][ni][1] = bhi[ni];
                acc[mi][ni][2] = blo[ni]; acc[mi][ni][3] = bhi[ni];
            }
        gemm_mma<140, 136, false>(sA, sWa, 16, acc, wr, wc, lane);
        __syncthreads();
        // chunk B: nf[dst] + radial col + zero pad
        for (int i = tid; i < 128 * 32; i += 256) {
            int row = i >> 5, c4 = (i & 31) * 4;
            const float4 v = *(const float4*)&nf[(size_t)sDst[row] * 128 + c4];
            float* p = &sA[row * 140 + c4];
            p[0] = tf32f(v.x); p[1] = tf32f(v.y); p[2] = tf32f(v.z); p[3] = tf32f(v.w);
        }
        if (tid < 128) {
            float* p = &sA[tid * 140 + 128];
            p[0] = tf32f(sRad[tid]);
            p[1] = 0.f; p[2] = 0.f; p[3] = 0.f;
            p[4] = 0.f; p[5] = 0.f; p[6] = 0.f; p[7] = 0.f;
        }
        __syncthreads();
        gemm_mma<140, 136, false>(sA, sWb, 17, acc, wr, wc, lane);

        // epilogue: silu, round to tf32 (g_h1 feeds next GEMM), store
        {
            const int g = lane >> 2, t2 = 2 * (lane & 3);
#pragma unroll
            for (int mi = 0; mi < 2; ++mi) {
                int r = be + wr * 32 + mi * 16 + g;
#pragma unroll
                for (int ni = 0; ni < 8; ++ni) {
                    int c = wc * 64 + ni * 8 + t2;
                    float2 v0, v1;
                    v0.x = tf32f(silu_f(acc[mi][ni][0]));
                    v0.y = tf32f(silu_f(acc[mi][ni][1]));
                    v1.x = tf32f(silu_f(acc[mi][ni][2]));
                    v1.y = tf32f(silu_f(acc[mi][ni][3]));
                    *(float2*)&g_h1[(size_t)r * 128 + c] = v0;
                    *(float2*)&g_h1[(size_t)(r + 8) * 128 + c] = v1;
                }
            }
        }
        __syncthreads();
    }
}

// ---------------- k_edge2: h2 = silu(h1@W2+b2) scatter; coord path ----------------
// smem: sW2[128][136] | sW5[128][136] | sA[128][132] | sB2,sB5,sW6,sCW[128] | idx
__global__ void __launch_bounds__(256, 1)
k_edge2(const float* __restrict__ coord,
        const int* __restrict__ src, const int* __restrict__ dst,
        const float* __restrict__ W2, const float* __restrict__ b2,
        const float* __restrict__ W5, const float* __restrict__ b5,
        const float* __restrict__ W6) {
    extern __shared__ float sm[];
    float* sW2 = sm;                       // 128*136
    float* sW5 = sW2 + 128 * 136;          // 128*136
    float* sA  = sW5 + 128 * 136;          // 128*132 (h1, then h2 fp32)
    float* sB2 = sA + 128 * 132;           // 128
    float* sB5 = sB2 + 128;                // 128
    float* sW6 = sB5 + 128;                // 128
    float* sCW = sW6 + 128;                // 128
    int* sSrc = (int*)(sCW + 128);         // 128
    int* sDst = sSrc + 128;                // 128

    const int tid = threadIdx.x, lane = tid & 31, wid = tid >> 5;
    const int wr = wid & 3, wc = wid >> 2;
    const int g = lane >> 2, t2 = 2 * (lane & 3);

    for (int i = tid; i < 128 * 128; i += 256) {
        int k = i >> 7, n = i & 127;
        sW2[k * 136 + n] = tf32f(W2[i]);
        sW5[k * 136 + n] = tf32f(W5[i]);
    }
    if (tid < 128) { sB2[tid] = b2[tid]; sB5[tid] = b5[tid]; sW6[tid] = W6[tid]; }
    __syncthreads();

    const int ntiles = NE / 128;
    for (int tile = blockIdx.x; tile < ntiles; tile += gridDim.x) {
        const int be = tile * 128;
        if (tid < 128) {
            sSrc[tid] = src[be + tid];
            sDst[tid] = dst[be + tid];
            sCW[tid] = 0.f;
        }
        // load h1 tile (already tf32-rounded)
        for (int i = tid; i < 128 * 32; i += 256) {
            int row = i >> 5, c4 = (i & 31) * 4;
            *(float4*)&sA[row * 132 + c4] = *(const float4*)&g_h1[(size_t)(be + row) * 128 + c4];
        }
        __syncthreads();

        // GEMM1: h2 = silu(h1 @ W2 + b2)
        float acc[2][8][4];
#pragma unroll
        for (int mi = 0; mi < 2; ++mi)
#pragma unroll
            for (int ni = 0; ni < 8; ++ni) {
                int c = wc * 64 + ni * 8 + t2;
                acc[mi][ni][0] = sB2[c]; acc[mi][ni][1] = sB2[c + 1];
                acc[mi][ni][2] = sB2[c]; acc[mi][ni][3] = sB2[c + 1];
            }
        gemm_mma<132, 136, false>(sA, sW2, 16, acc, wr, wc, lane);
        __syncthreads();   // all reads of sA(h1) done

        // write h2 (fp32) into sA
#pragma unroll
        for (int mi = 0; mi < 2; ++mi) {
            int r = wr * 32 + mi * 16 + g;
#pragma unroll
            for (int ni = 0; ni < 8; ++ni) {
                int c = wc * 64 + ni * 8 + t2;
                float2 v0, v1;
                v0.x = silu_f(acc[mi][ni][0]); v0.y = silu_f(acc[mi][ni][1]);
                v1.x = silu_f(acc[mi][ni][2]); v1.y = silu_f(acc[mi][ni][3]);
                *(float2*)&sA[r * 132 + c] = v0;
                *(float2*)&sA[(r + 8) * 132 + c] = v1;
            }
        }
        __syncthreads();

        // GEMM2: h3pre = h2 @ W5 + b5 (cvt A on the fly)
#pragma unroll
        for (int mi = 0; mi < 2; ++mi)
#pragma unroll
            for (int ni = 0; ni < 8; ++ni) {
                int c = wc * 64 + ni * 8 + t2;
                acc[mi][ni][0] = sB5[c]; acc[mi][ni][1] = sB5[c + 1];
                acc[mi][ni][2] = sB5[c]; acc[mi][ni][3] = sB5[c + 1];
            }
        gemm_mma<132, 136, true>(sA, sW5, 16, acc, wr, wc, lane);

        // scatter h2 -> g_hneigh with vector reduction atomics
        for (int i = tid; i < 128 * 32; i += 256) {
            int row = i >> 5, c4 = (i & 31) * 4;
            const float4 v = *(const float4*)&sA[row * 132 + c4];
            float* p = &g_hneigh[(size_t)sDst[row] * 128 + c4];
            asm volatile("red.global.add.v4.f32 [%0], {%1,%2,%3,%4};"
                         :: "l"(p), "f"(v.x), "f"(v.y), "f"(v.z), "f"(v.w) : "memory");
        }

        // dot: cw[row] = sum_c silu(h3pre) * W6[c]
#pragma unroll
        for (int mi = 0; mi < 2; ++mi) {
            float pr0 = 0.f, pr1 = 0.f;
#pragma unroll
            for (int ni = 0; ni < 8; ++ni) {
                int c = wc * 64 + ni * 8 + t2;
                float w0 = sW6[c], w1 = sW6[c + 1];
                pr0 += silu_f(acc[mi][ni][0]) * w0 + silu_f(acc[mi][ni][1]) * w1;
                pr1 += silu_f(acc[mi][ni][2]) * w0 + silu_f(acc[mi][ni][3]) * w1;
            }
            pr0 += __shfl_xor_sync(0xffffffffu, pr0, 1);
            pr0 += __shfl_xor_sync(0xffffffffu, pr0, 2);
            pr1 += __shfl_xor_sync(0xffffffffu, pr1, 1);
            pr1 += __shfl_xor_sync(0xffffffffu, pr1, 2);
            if ((lane & 3) == 0) {
                int r = wr * 32 + mi * 16 + g;
                atomicAdd(&sCW[r], pr0);
                atomicAdd(&sCW[r + 8], pr1);
            }
        }
        __syncthreads();

        if (tid < 128) {
            int s = sSrc[tid], d = sDst[tid];
            float dx = coord[s * 3 + 0] - coord[d * 3 + 0];
            float dy = coord[s * 3 + 1] - coord[d * 3 + 1];
            float dz = coord[s * 3 + 2] - coord[d * 3 + 2];
            float r  = dx * dx + dy * dy + dz * dz;
            float inv = 1.0f / (sqrtf(r + 1e-6f) + 1e-6f);
            float cws = sCW[tid] * inv;
            atomicAdd(&g_xsum[d * 3 + 0], cws * dx);
            atomicAdd(&g_xsum[d * 3 + 1], cws * dy);
            atomicAdd(&g_xsum[d * 3 + 2], cws * dz);
        }
        __syncthreads();
    }
}

// ---------------- k_node1: t1 = silu([nf|h_neigh] @ W3 + b3) -> g_h1 ----------------
__global__ void __launch_bounds__(256, 1)
k_node1(const float* __restrict__ nf, const float* __restrict__ W3,
        const float* __restrict__ b3) {
    extern __shared__ float sm[];
    float* sWa = sm;                       // 128*136
    float* sWb = sWa + 128 * 136;          // 128*136
    float* sA  = sWb + 128 * 136;          // 128*132
    float* sB  = sA + 128 * 132;           // 128

    const int tid = threadIdx.x, lane = tid & 31, wid = tid >> 5;
    const int wr = wid & 3, wc = wid >> 2;
    const int g = lane >> 2, t2 = 2 * (lane & 3);

    for (int i = tid; i < 128 * 128; i += 256) {
        int k = i >> 7, n = i & 127;
        sWa[k * 136 + n] = tf32f(W3[i]);
        sWb[k * 136 + n] = tf32f(W3[128 * 128 + i]);
    }
    if (tid < 128) sB[tid] = b3[tid];
    __syncthreads();

    const int ntiles = (NN + 127) / 128;
    for (int tile = blockIdx.x; tile < ntiles; tile += gridDim.x) {
        const int bn = tile * 128;
        // chunk A: nf
        for (int i = tid; i < 128 * 32; i += 256) {
            int row = i >> 5, c4 = (i & 31) * 4;
            int n = bn + row;
            float4 v = make_float4(0.f, 0.f, 0.f, 0.f);
            if (n < NN) v = *(const float4*)&nf[(size_t)n * 128 + c4];
            float* p = &sA[row * 132 + c4];
            p[0] = tf32f(v.x); p[1] = tf32f(v.y); p[2] = tf32f(v.z); p[3] = tf32f(v.w);
        }
        __syncthreads();

        float acc[2][8][4];
#pragma unroll
        for (int mi = 0; mi < 2; ++mi)
#pragma unroll
            for (int ni = 0; ni < 8; ++ni) {
                int c = wc * 64 + ni * 8 + t2;
                acc[mi][ni][0] = sB[c]; acc[mi][ni][1] = sB[c + 1];
                acc[mi][ni][2] = sB[c]; acc[mi][ni][3] = sB[c + 1];
            }
        gemm_mma<132, 136, false>(sA, sWa, 16, acc, wr, wc, lane);
        __syncthreads();
        // chunk B: h_neigh
        for (int i = tid; i < 128 * 32; i += 256) {
            int row = i >> 5, c4 = (i & 31) * 4;
            int n = bn + row;
            float4 v = make_float4(0.f, 0.f, 0.f, 0.f);
            if (n < NN) v = *(const float4*)&g_hneigh[(size_t)n * 128 + c4];
            float* p = &sA[row * 132 + c4];
            p[0] = tf32f(v.x); p[1] = tf32f(v.y); p[2] = tf32f(v.z); p[3] = tf32f(v.w);
        }
        __syncthreads();
        gemm_mma<132, 136, false>(sA, sWb, 16, acc, wr, wc, lane);

#pragma unroll
        for (int mi = 0; mi < 2; ++mi) {
            int r = bn + wr * 32 + mi * 16 + g;
#pragma unroll
            for (int ni = 0; ni < 8; ++ni) {
                int c = wc * 64 + ni * 8 + t2;
                if (r < NN) {
                    float2 v0;
                    v0.x = tf32f(silu_f(acc[mi][ni][0]));
                    v0.y = tf32f(silu_f(acc[mi][ni][1]));
                    *(float2*)&g_h1[(size_t)r * 128 + c] = v0;
                }
                if (r + 8 < NN) {
                    float2 v1;
                    v1.x = tf32f(silu_f(acc[mi][ni][2]));
                    v1.y = tf32f(silu_f(acc[mi][ni][3]));
                    *(float2*)&g_h1[(size_t)(r + 8) * 128 + c] = v1;
                }
            }
        }
        __syncthreads();
    }
}

// ---------------- k_node2: h = t1 @ W4 + b4 -> out ----------------
__global__ void __launch_bounds__(256, 1)
k_node2(const float* __restrict__ W4, const float* __restrict__ b4,
        float* __restrict__ outh) {
    extern __shared__ float sm[];
    float* sW = sm;                        // 128*136
    float* sA = sW + 128 * 136;            // 128*132
    float* sB = sA + 128 * 132;            // 128

    const int tid = threadIdx.x, lane = tid & 31, wid = tid >> 5;
    const int wr = wid & 3, wc = wid >> 2;
    const int g = lane >> 2, t2 = 2 * (lane & 3);

    for (int i = tid; i < 128 * 128; i += 256) {
        int k = i >> 7, n = i & 127;
        sW[k * 136 + n] = tf32f(W4[i]);
    }
    if (tid < 128) sB[tid] = b4[tid];
    __syncthreads();

    const int ntiles = (NN + 127) / 128;
    for (int tile = blockIdx.x; tile < ntiles; tile += gridDim.x) {
        const int bn = tile * 128;
        for (int i = tid; i < 128 * 32; i += 256) {
            int row = i >> 5, c4 = (i & 31) * 4;
            int n = bn + row;
            float4 v = make_float4(0.f, 0.f, 0.f, 0.f);
            if (n < NN) v = *(const float4*)&g_h1[(size_t)n * 128 + c4];
            *(float4*)&sA[row * 132 + c4] = v;
        }
        __syncthreads();

        float acc[2][8][4];
#pragma unroll
        for (int mi = 0; mi < 2; ++mi)
#pragma unroll
            for (int ni = 0; ni < 8; ++ni) {
                int c = wc * 64 + ni * 8 + t2;
                acc[mi][ni][0] = sB[c]; acc[mi][ni][1] = sB[c + 1];
                acc[mi][ni][2] = sB[c]; acc[mi][ni][3] = sB[c + 1];
            }
        gemm_mma<132, 136, false>(sA, sW, 16, acc, wr, wc, lane);

#pragma unroll
        for (int mi = 0; mi < 2; ++mi) {
            int r = bn + wr * 32 + mi * 16 + g;
#pragma unroll
            for (int ni = 0; ni < 8; ++ni) {
                int c = wc * 64 + ni * 8 + t2;
                if (r < NN)
                    *(float2*)&outh[(size_t)r * 128 + c] =
                        make_float2(acc[mi][ni][0], acc[mi][ni][1]);
                if (r + 8 < NN)
                    *(float2*)&outh[(size_t)(r + 8) * 128 + c] =
                        make_float2(acc[mi][ni][2], acc[mi][ni][3]);
            }
        }
        __syncthreads();
    }
}

// ---------------- k_x / k_fin / k_norm ----------------
__global__ void k_x(const float* __restrict__ coord, float* __restrict__ outx) {
    __shared__ float sred[6];
    int tid = threadIdx.x;
    if (tid < 6) sred[tid] = 0.f;
    __syncthreads();
    float ls[6] = {0.f, 0.f, 0.f, 0.f, 0.f, 0.f};
    int stride = gridDim.x * blockDim.x;
    for (int n = blockIdx.x * blockDim.x + tid; n < NN; n += stride) {
        float deg = fmaxf(g_deg[n], 1.0f);
        float invd = 1.0f / deg;
#pragma unroll
        for (int d = 0; d < 3; ++d) {
            float x = coord[n * 3 + d] + g_xsum[n * 3 + d] * invd;
            outx[n * 3 + d] = x;
            ls[d] += x;
            ls[3 + d] += x * x;
        }
    }
#pragma unroll
    for (int k = 0; k < 6; ++k) atomicAdd(&sred[k], ls[k]);
    __syncthreads();
    if (tid < 6) atomicAdd(&g_red[tid], sred[tid]);
}

__global__ void k_fin() {
    int t = threadIdx.x;
    if (t < 3) {
        float mean = g_red[t] / (float)NN;
        float m2   = g_red[3 + t] / (float)NN;
        float var  = m2 - mean * mean;
        g_red[8 + t]  = mean;
        g_red[11 + t] = 1.0f / (sqrtf(var + 1e-6f) + 1e-6f);
    }
}

__global__ void k_norm(float* __restrict__ outx) {
    int stride = gridDim.x * blockDim.x;
    for (int i = blockIdx.x * blockDim.x + threadIdx.x; i < NN * 3; i += stride) {
        int d = i % 3;
        outx[i] = (outx[i] - g_red[8 + d]) * g_red[11 + d];
    }
}

// ---------------- launch ----------------
extern "C" void kernel_launch(void* const* d_in, const int* in_sizes, int n_in,
                              void* d_out, int out_size) {
    const float* nf    = (const float*)d_in[0];
    const float* coord = (const float*)d_in[1];
    const int*   src   = (const int*)d_in[2];
    const int*   dst   = (const int*)d_in[3];
    const float* W1 = (const float*)d_in[4];
    const float* b1 = (const float*)d_in[5];
    const float* W2 = (const float*)d_in[6];
    const float* b2 = (const float*)d_in[7];
    const float* W3 = (const float*)d_in[8];
    const float* b3 = (const float*)d_in[9];
    const float* W4 = (const float*)d_in[10];
    const float* b4 = (const float*)d_in[11];
    const float* W5 = (const float*)d_in[12];
    const float* b5 = (const float*)d_in[13];
    const float* W6 = (const float*)d_in[14];

    float* outh = (float*)d_out;
    float* outx = outh + (size_t)NN * C;

    const int SM_E1 = (128 * 136 + 136 * 136 + 128 * 140 + 256) * 4 + 2 * 128 * 4;
    const int SM_E2 = (128 * 136 * 2 + 128 * 132 + 512) * 4 + 2 * 128 * 4;
    const int SM_N1 = (128 * 136 * 2 + 128 * 132 + 128) * 4;
    const int SM_N2 = (128 * 136 + 128 * 132 + 128) * 4;

    cudaFuncSetAttribute(k_edge1, cudaFuncAttributeMaxDynamicSharedMemorySize, SM_E1);
    cudaFuncSetAttribute(k_edge2, cudaFuncAttributeMaxDynamicSharedMemorySize, SM_E2);
    cudaFuncSetAttribute(k_node1, cudaFuncAttributeMaxDynamicSharedMemorySize, SM_N1);
    cudaFuncSetAttribute(k_node2, cudaFuncAttributeMaxDynamicSharedMemorySize, SM_N2);

    k_init<<<2048, 256>>>();
    k_deg<<<512, 256>>>(dst);
    k_edge1<<<148, 256, SM_E1>>>(nf, coord, src, dst, W1, b1);
    k_edge2<<<148, 256, SM_E2>>>(coord, src, dst, W2, b2, W5, b5, W6);
    k_node1<<<148, 256, SM_N1>>>(nf, W3, b3);
    k_node2<<<148, 256, SM_N2>>>(W4, b4, outh);
    k_x<<<160, 256>>>(coord, outx);
    k_fin<<<1, 32>>>();
    k_norm<<<160, 256>>>(outx);
}

// round 6
// speedup vs baseline: 4.0896x; 1.2224x over previous
#include <cuda_runtime.h>
#include <cuda_bf16.h>
#include <math.h>

#define NN 50000
#define NE 800000
#define C  128

// ---------------- device scratch ----------------
static __device__ float g_h1[(size_t)NE * C];    // edge hidden (paired layout) / node t1 reuse (row-major)
static __device__ float g_hneigh[(size_t)NN * C];
static __device__ float g_xsum[NN * 3];
static __device__ float g_deg[NN];
static __device__ float g_red[16];

__device__ __forceinline__ float silu_f(float v) {
    return v / (1.0f + __expf(-v));
}
__device__ __forceinline__ float tf32f(float x) {
    unsigned u;
    asm("cvt.rna.tf32.f32 %0, %1;" : "=r"(u) : "f"(x));
    return __uint_as_float(u);
}
__device__ __forceinline__ unsigned fu(float x) { return __float_as_uint(x); }

__device__ __forceinline__ void mma8(float* d, const unsigned* a, unsigned b0, unsigned b1) {
    asm volatile(
        "mma.sync.aligned.m16n8k8.row.col.f32.tf32.tf32.f32 "
        "{%0,%1,%2,%3}, {%4,%5,%6,%7}, {%8,%9}, {%0,%1,%2,%3};"
        : "+f"(d[0]), "+f"(d[1]), "+f"(d[2]), "+f"(d[3])
        : "r"(a[0]), "r"(a[1]), "r"(a[2]), "r"(a[3]), "r"(b0), "r"(b1));
}

__device__ __forceinline__ void cp16(float* dstS, const float* srcG) {
    unsigned s = (unsigned)__cvta_generic_to_shared(dstS);
    asm volatile("cp.async.ca.shared.global [%0], [%1], 16;" :: "r"(s), "l"(srcG));
}
__device__ __forceinline__ void cpwait() {
    asm volatile("cp.async.commit_group;\ncp.async.wait_group 0;" ::: "memory");
}

// =============== paired-k W layout ===============
// sWp[(kc*128 + c)*8 + 2*(k&3) + ((k>>2)&1)] holds W[k][c], kc = k>>3.
// B-fragment (k=t, k=t+4) for col c is one aligned float2.

template<int SA, bool CVTA>
__device__ __forceinline__ void gemm_rApB(const float* __restrict__ sA,
                                          const float* __restrict__ sWp,
                                          int kchunks, float (&acc)[2][8][4],
                                          int wr, int wc, int lane) {
    const int g = lane >> 2, t = lane & 3;
    const float* ar = sA + (wr * 32 + g) * SA + t;
    const float* bb = sWp + (wc * 64 + g) * 8 + 2 * t;
#pragma unroll 4
    for (int kc = 0; kc < kchunks; ++kc) {
        const float* ap = ar + kc * 8;
        float a00 = ap[0],       a01 = ap[8 * SA],       a02 = ap[4],       a03 = ap[8 * SA + 4];
        float a10 = ap[16 * SA], a11 = ap[24 * SA],      a12 = ap[16 * SA + 4], a13 = ap[24 * SA + 4];
        if (CVTA) {
            a00 = tf32f(a00); a01 = tf32f(a01); a02 = tf32f(a02); a03 = tf32f(a03);
            a10 = tf32f(a10); a11 = tf32f(a11); a12 = tf32f(a12); a13 = tf32f(a13);
        }
        unsigned A0[4] = {fu(a00), fu(a01), fu(a02), fu(a03)};
        unsigned A1[4] = {fu(a10), fu(a11), fu(a12), fu(a13)};
        const float* bp = bb + kc * 1024;
#pragma unroll
        for (int ni = 0; ni < 8; ++ni) {
            float2 b = *(const float2*)(bp + ni * 64);
            mma8(acc[0][ni], A0, fu(b.x), fu(b.y));
            mma8(acc[1][ni], A1, fu(b.x), fu(b.y));
        }
    }
}

// A paired layout direct from global (g_h1 tile), depth-1 register prefetch.
__device__ __forceinline__ void gemm_gApB(const float* __restrict__ gA,
                                          const float* __restrict__ sWp,
                                          float (&acc)[2][8][4],
                                          int wr, int wc, int lane) {
    const int g = lane >> 2, t = lane & 3;
    const float* ar = gA + (wr * 32 + g) * 128 + 2 * t;
    const float* bb = sWp + (wc * 64 + g) * 8 + 2 * t;
    float2 c0 = __ldg((const float2*)(ar));
    float2 c1 = __ldg((const float2*)(ar + 8 * 128));
    float2 c2 = __ldg((const float2*)(ar + 16 * 128));
    float2 c3 = __ldg((const float2*)(ar + 24 * 128));
#pragma unroll 4
    for (int kc = 0; kc < 16; ++kc) {
        float2 a0 = c0, a1 = c1, a2 = c2, a3 = c3;
        const float* nx = ar + ((kc + 1) & 15) * 8;
        c0 = __ldg((const float2*)(nx));
        c1 = __ldg((const float2*)(nx + 8 * 128));
        c2 = __ldg((const float2*)(nx + 16 * 128));
        c3 = __ldg((const float2*)(nx + 24 * 128));
        unsigned A0[4] = {fu(a0.x), fu(a1.x), fu(a0.y), fu(a1.y)};
        unsigned A1[4] = {fu(a2.x), fu(a3.x), fu(a2.y), fu(a3.y)};
        const float* bp = bb + kc * 1024;
#pragma unroll
        for (int ni = 0; ni < 8; ++ni) {
            float2 b = *(const float2*)(bp + ni * 64);
            mma8(acc[0][ni], A0, fu(b.x), fu(b.y));
            mma8(acc[1][ni], A1, fu(b.x), fu(b.y));
        }
    }
}

// Node-kernel GEMM: A row-major, W padded row-major [k][SW].
template<int SA, int SW, bool CVT>
__device__ __forceinline__ void gemm_mma(const float* __restrict__ sA,
                                         const float* __restrict__ sW,
                                         int kchunks, float (&acc)[2][8][4],
                                         int wr, int wc, int lane) {
    const int g = lane >> 2, t = lane & 3;
    const float* a0p = sA + (wr * 32 + g) * SA + t;
    const float* bB  = sW + t * SW + wc * 64 + g;
#pragma unroll 4
    for (int kc = 0; kc < kchunks; ++kc) {
        unsigned A0[4], A1[4];
        const float* ap = a0p + kc * 8;
        const float* ap1 = ap + 16 * SA;
        if (CVT) {
            A0[0] = fu(tf32f(ap[0]));      A0[1] = fu(tf32f(ap[8 * SA]));
            A0[2] = fu(tf32f(ap[4]));      A0[3] = fu(tf32f(ap[8 * SA + 4]));
            A1[0] = fu(tf32f(ap1[0]));     A1[1] = fu(tf32f(ap1[8 * SA]));
            A1[2] = fu(tf32f(ap1[4]));     A1[3] = fu(tf32f(ap1[8 * SA + 4]));
        } else {
            A0[0] = fu(ap[0]);      A0[1] = fu(ap[8 * SA]);
            A0[2] = fu(ap[4]);      A0[3] = fu(ap[8 * SA + 4]);
            A1[0] = fu(ap1[0]);     A1[1] = fu(ap1[8 * SA]);
            A1[2] = fu(ap1[4]);     A1[3] = fu(ap1[8 * SA + 4]);
        }
        const float* bp = bB + kc * 8 * SW;
#pragma unroll
        for (int ni = 0; ni < 8; ++ni) {
            unsigned b0 = fu(bp[ni * 8]);
            unsigned b1 = fu(bp[4 * SW + ni * 8]);
            mma8(acc[0][ni], A0, b0, b1);
            mma8(acc[1][ni], A1, b0, b1);
        }
    }
}

// ---------------- k_init ----------------
__global__ void k_init() {
    const long NC = (long)NN * C, N3 = NN * 3;
    const long TOT = NC + N3 + NN + 16;
    long stride = (long)gridDim.x * blockDim.x;
    for (long i = (long)blockIdx.x * blockDim.x + threadIdx.x; i < TOT; i += stride) {
        if (i < NC) g_hneigh[i] = 0.f;
        else if (i < NC + N3) g_xsum[i - NC] = 0.f;
        else if (i < NC + N3 + NN) g_deg[i - NC - N3] = 0.f;
        else g_red[i - NC - N3 - NN] = 0.f;
    }
}

// ---------------- k_edge1 ----------------
__global__ void __launch_bounds__(256, 1)
k_edge1(const float* __restrict__ nf, const float* __restrict__ coord,
        const int* __restrict__ src, const int* __restrict__ dst,
        const float* __restrict__ W1, const float* __restrict__ b1) {
    extern __shared__ float sm[];
    float* sWa = sm;                        // 16*128*8 = 16384
    float* sWb = sWa + 16384;               // 17*128*8 = 17408
    float* sA  = sWb + 17408;               // 128*140 = 17920
    float* sRad = sA + 17920;               // 128
    int* sSrc = (int*)(sRad + 128);         // 128
    int* sDst = sSrc + 128;                 // 128

    const int tid = threadIdx.x, lane = tid & 31, wid = tid >> 5;
    const int wr = wid & 3, wc = wid >> 2;
    const int g = lane >> 2, t = lane & 3;

    for (int i = tid; i < 17408; i += 256) sWb[i] = 0.f;
    __syncthreads();
    for (int i = tid; i < 128 * 128; i += 256) {
        int k = i >> 7, c = i & 127;
        int pos = ((k >> 3) * 128 + c) * 8 + 2 * (k & 3) + ((k >> 2) & 1);
        sWa[pos] = tf32f(W1[i]);
        sWb[pos] = tf32f(W1[128 * 128 + i]);
    }
    if (tid < 128) sWb[16384 + tid * 8] = tf32f(W1[256 * 128 + tid]);  // k=128 row
    __syncthreads();

    float blo[8], bhi[8];
    {
        int cb = wc * 64 + 2 * t;
#pragma unroll
        for (int ni = 0; ni < 8; ++ni) {
            blo[ni] = __ldg(&b1[cb + ni * 8]);
            bhi[ni] = __ldg(&b1[cb + ni * 8 + 1]);
        }
    }
    const int p0 = (t & 1) * 4 + (t >> 1);   // paired position of col offset 2t

    const int ntiles = NE / 128;
    for (int tile = blockIdx.x; tile < ntiles; tile += gridDim.x) {
        const int be = tile * 128;
        if (tid < 128) {
            int e = be + tid;
            int s = src[e], d = dst[e];
            sSrc[tid] = s; sDst[tid] = d;
            atomicAdd(&g_deg[d], 1.0f);
            float dx = coord[s * 3 + 0] - coord[d * 3 + 0];
            float dy = coord[s * 3 + 1] - coord[d * 3 + 1];
            float dz = coord[s * 3 + 2] - coord[d * 3 + 2];
            sRad[tid] = dx * dx + dy * dy + dz * dz;
        }
        __syncthreads();

        for (int i = tid; i < 4096; i += 256) {
            int row = i >> 5, c4 = (i & 31) * 4;
            cp16(&sA[row * 140 + c4], &nf[(size_t)sSrc[row] * 128 + c4]);
        }
        cpwait();
        __syncthreads();

        float acc[2][8][4];
#pragma unroll
        for (int mi = 0; mi < 2; ++mi)
#pragma unroll
            for (int ni = 0; ni < 8; ++ni) {
                acc[mi][ni][0] = blo[ni]; acc[mi][ni][1] = bhi[ni];
                acc[mi][ni][2] = blo[ni]; acc[mi][ni][3] = bhi[ni];
            }
        gemm_rApB<140, true>(sA, sWa, 16, acc, wr, wc, lane);
        __syncthreads();

        for (int i = tid; i < 4096; i += 256) {
            int row = i >> 5, c4 = (i & 31) * 4;
            cp16(&sA[row * 140 + c4], &nf[(size_t)sDst[row] * 128 + c4]);
        }
        if (tid < 128) {
            float* p = &sA[tid * 140 + 128];
            *(float4*)p = make_float4(sRad[tid], 0.f, 0.f, 0.f);
            *(float4*)(p + 4) = make_float4(0.f, 0.f, 0.f, 0.f);
        }
        cpwait();
        __syncthreads();
        gemm_rApB<140, true>(sA, sWb, 17, acc, wr, wc, lane);

#pragma unroll
        for (int mi = 0; mi < 2; ++mi) {
            size_t rb = (size_t)(be + wr * 32 + mi * 16 + g) * 128 + wc * 64;
#pragma unroll
            for (int ni = 0; ni < 8; ++ni) {
                size_t o = rb + ni * 8 + p0;
                g_h1[o]     = tf32f(silu_f(acc[mi][ni][0]));
                g_h1[o + 2] = tf32f(silu_f(acc[mi][ni][1]));
                g_h1[o + 8 * 128]     = tf32f(silu_f(acc[mi][ni][2]));
                g_h1[o + 8 * 128 + 2] = tf32f(silu_f(acc[mi][ni][3]));
            }
        }
    }
}

// ---------------- k_edge2 ----------------
__global__ void __launch_bounds__(256, 1)
k_edge2(const float* __restrict__ coord,
        const int* __restrict__ src, const int* __restrict__ dst,
        const float* __restrict__ W2, const float* __restrict__ b2,
        const float* __restrict__ W5, const float* __restrict__ b5,
        const float* __restrict__ W6) {
    extern __shared__ float sm[];
    float* sW2p = sm;                      // 16384
    float* sW5p = sW2p + 16384;            // 16384
    float* sH   = sW5p + 16384;            // 128*132 = 16896
    float* sCW  = sH + 16896;              // 128
    int* sSrc = (int*)(sCW + 128);         // 128
    int* sDst = sSrc + 128;                // 128

    const int tid = threadIdx.x, lane = tid & 31, wid = tid >> 5;
    const int wr = wid & 3, wc = wid >> 2;
    const int g = lane >> 2, t = lane & 3;

    for (int i = tid; i < 128 * 128; i += 256) {
        int k = i >> 7, c = i & 127;
        int pos = ((k >> 3) * 128 + c) * 8 + 2 * (k & 3) + ((k >> 2) & 1);
        sW2p[pos] = tf32f(W2[i]);
        sW5p[pos] = tf32f(W5[i]);
    }
    __syncthreads();

    float b2lo[8], b2hi[8], b5lo[8], b5hi[8], w6lo[8], w6hi[8];
    {
        int cb = wc * 64 + 2 * t;
#pragma unroll
        for (int ni = 0; ni < 8; ++ni) {
            b2lo[ni] = __ldg(&b2[cb + ni * 8]); b2hi[ni] = __ldg(&b2[cb + ni * 8 + 1]);
            b5lo[ni] = __ldg(&b5[cb + ni * 8]); b5hi[ni] = __ldg(&b5[cb + ni * 8 + 1]);
            w6lo[ni] = __ldg(&W6[cb + ni * 8]); w6hi[ni] = __ldg(&W6[cb + ni * 8 + 1]);
        }
    }

    const int ntiles = NE / 128;
    for (int tile = blockIdx.x; tile < ntiles; tile += gridDim.x) {
        const int be = tile * 128;
        if (tid < 128) {
            sSrc[tid] = src[be + tid];
            sDst[tid] = dst[be + tid];
            sCW[tid] = 0.f;
        }

        float acc[2][8][4];
#pragma unroll
        for (int mi = 0; mi < 2; ++mi)
#pragma unroll
            for (int ni = 0; ni < 8; ++ni) {
                acc[mi][ni][0] = b2lo[ni]; acc[mi][ni][1] = b2hi[ni];
                acc[mi][ni][2] = b2lo[ni]; acc[mi][ni][3] = b2hi[ni];
            }
        gemm_gApB(g_h1 + (size_t)tile * 16384, sW2p, acc, wr, wc, lane);

#pragma unroll
        for (int mi = 0; mi < 2; ++mi) {
            int r = wr * 32 + mi * 16 + g;
#pragma unroll
            for (int ni = 0; ni < 8; ++ni) {
                int c = wc * 64 + ni * 8 + 2 * t;
                *(float2*)&sH[r * 132 + c] =
                    make_float2(silu_f(acc[mi][ni][0]), silu_f(acc[mi][ni][1]));
                *(float2*)&sH[(r + 8) * 132 + c] =
                    make_float2(silu_f(acc[mi][ni][2]), silu_f(acc[mi][ni][3]));
            }
        }
        __syncthreads();   // (1) h2 + indices ready

        float acc2[2][8][4];
#pragma unroll
        for (int mi = 0; mi < 2; ++mi)
#pragma unroll
            for (int ni = 0; ni < 8; ++ni) {
                acc2[mi][ni][0] = b5lo[ni]; acc2[mi][ni][1] = b5hi[ni];
                acc2[mi][ni][2] = b5lo[ni]; acc2[mi][ni][3] = b5hi[ni];
            }
        gemm_rApB<132, true>(sH, sW5p, 16, acc2, wr, wc, lane);

        for (int i = tid; i < 4096; i += 256) {
            int row = i >> 5, c4 = (i & 31) * 4;
            const float4 v = *(const float4*)&sH[row * 132 + c4];
            float* p = &g_hneigh[(size_t)sDst[row] * 128 + c4];
            asm volatile("red.global.add.v4.f32 [%0], {%1,%2,%3,%4};"
                         :: "l"(p), "f"(v.x), "f"(v.y), "f"(v.z), "f"(v.w) : "memory");
        }

#pragma unroll
        for (int mi = 0; mi < 2; ++mi) {
            float pr0 = 0.f, pr1 = 0.f;
#pragma unroll
            for (int ni = 0; ni < 8; ++ni) {
                pr0 += silu_f(acc2[mi][ni][0]) * w6lo[ni] + silu_f(acc2[mi][ni][1]) * w6hi[ni];
                pr1 += silu_f(acc2[mi][ni][2]) * w6lo[ni] + silu_f(acc2[mi][ni][3]) * w6hi[ni];
            }
            pr0 += __shfl_xor_sync(0xffffffffu, pr0, 1);
            pr0 += __shfl_xor_sync(0xffffffffu, pr0, 2);
            pr1 += __shfl_xor_sync(0xffffffffu, pr1, 1);
            pr1 += __shfl_xor_sync(0xffffffffu, pr1, 2);
            if (t == 0) {
                int r = wr * 32 + mi * 16 + g;
                atomicAdd(&sCW[r], pr0);
                atomicAdd(&sCW[r + 8], pr1);
            }
        }
        __syncthreads();   // (2) sCW complete, scatter reads of sH done

        if (tid < 128) {
            int s = sSrc[tid], d = sDst[tid];
            float dx = coord[s * 3 + 0] - coord[d * 3 + 0];
            float dy = coord[s * 3 + 1] - coord[d * 3 + 1];
            float dz = coord[s * 3 + 2] - coord[d * 3 + 2];
            float r  = dx * dx + dy * dy + dz * dz;
            float inv = 1.0f / (sqrtf(r + 1e-6f) + 1e-6f);
            float cws = sCW[tid] * inv;
            atomicAdd(&g_xsum[d * 3 + 0], cws * dx);
            atomicAdd(&g_xsum[d * 3 + 1], cws * dy);
            atomicAdd(&g_xsum[d * 3 + 2], cws * dz);
        }
        __syncthreads();   // (3) protect sCW/sH for next tile
    }
}

// ---------------- k_node1 ----------------
__global__ void __launch_bounds__(256, 1)
k_node1(const float* __restrict__ nf, const float* __restrict__ W3,
        const float* __restrict__ b3) {
    extern __shared__ float sm[];
    float* sWa = sm;                       // 128*136
    float* sWb = sWa + 128 * 136;          // 128*136
    float* sA  = sWb + 128 * 136;          // 128*132
    float* sB  = sA + 128 * 132;           // 128

    const int tid = threadIdx.x, lane = tid & 31, wid = tid >> 5;
    const int wr = wid & 3, wc = wid >> 2;
    const int g = lane >> 2, t2 = 2 * (lane & 3);

    for (int i = tid; i < 128 * 128; i += 256) {
        int k = i >> 7, n = i & 127;
        sWa[k * 136 + n] = tf32f(W3[i]);
        sWb[k * 136 + n] = tf32f(W3[128 * 128 + i]);
    }
    if (tid < 128) sB[tid] = b3[tid];
    __syncthreads();

    const int ntiles = (NN + 127) / 128;
    for (int tile = blockIdx.x; tile < ntiles; tile += gridDim.x) {
        const int bn = tile * 128;
        for (int i = tid; i < 128 * 32; i += 256) {
            int row = i >> 5, c4 = (i & 31) * 4;
            int n = bn + row;
            float4 v = make_float4(0.f, 0.f, 0.f, 0.f);
            if (n < NN) v = *(const float4*)&nf[(size_t)n * 128 + c4];
            float* p = &sA[row * 132 + c4];
            p[0] = tf32f(v.x); p[1] = tf32f(v.y); p[2] = tf32f(v.z); p[3] = tf32f(v.w);
        }
        __syncthreads();

        float acc[2][8][4];
#pragma unroll
        for (int mi = 0; mi < 2; ++mi)
#pragma unroll
            for (int ni = 0; ni < 8; ++ni) {
                int c = wc * 64 + ni * 8 + t2;
                acc[mi][ni][0] = sB[c]; acc[mi][ni][1] = sB[c + 1];
                acc[mi][ni][2] = sB[c]; acc[mi][ni][3] = sB[c + 1];
            }
        gemm_mma<132, 136, false>(sA, sWa, 16, acc, wr, wc, lane);
        __syncthreads();
        for (int i = tid; i < 128 * 32; i += 256) {
            int row = i >> 5, c4 = (i & 31) * 4;
            int n = bn + row;
            float4 v = make_float4(0.f, 0.f, 0.f, 0.f);
            if (n < NN) v = *(const float4*)&g_hneigh[(size_t)n * 128 + c4];
            float* p = &sA[row * 132 + c4];
            p[0] = tf32f(v.x); p[1] = tf32f(v.y); p[2] = tf32f(v.z); p[3] = tf32f(v.w);
        }
        __syncthreads();
        gemm_mma<132, 136, false>(sA, sWb, 16, acc, wr, wc, lane);

#pragma unroll
        for (int mi = 0; mi < 2; ++mi) {
            int r = bn + wr * 32 + mi * 16 + g;
#pragma unroll
            for (int ni = 0; ni < 8; ++ni) {
                int c = wc * 64 + ni * 8 + t2;
                if (r < NN)
                    *(float2*)&g_h1[(size_t)r * 128 + c] =
                        make_float2(tf32f(silu_f(acc[mi][ni][0])), tf32f(silu_f(acc[mi][ni][1])));
                if (r + 8 < NN)
                    *(float2*)&g_h1[(size_t)(r + 8) * 128 + c] =
                        make_float2(tf32f(silu_f(acc[mi][ni][2])), tf32f(silu_f(acc[mi][ni][3])));
            }
        }
        __syncthreads();
    }
}

// ---------------- k_node2 ----------------
__global__ void __launch_bounds__(256, 1)
k_node2(const float* __restrict__ W4, const float* __restrict__ b4,
        float* __restrict__ outh) {
    extern __shared__ float sm[];
    float* sW = sm;                        // 128*136
    float* sA = sW + 128 * 136;            // 128*132
    float* sB = sA + 128 * 132;            // 128

    const int tid = threadIdx.x, lane = tid & 31, wid = tid >> 5;
    const int wr = wid & 3, wc = wid >> 2;
    const int g = lane >> 2, t2 = 2 * (lane & 3);

    for (int i = tid; i < 128 * 128; i += 256) {
        int k = i >> 7, n = i & 127;
        sW[k * 136 + n] = tf32f(W4[i]);
    }
    if (tid < 128) sB[tid] = b4[tid];
    __syncthreads();

    const int ntiles = (NN + 127) / 128;
    for (int tile = blockIdx.x; tile < ntiles; tile += gridDim.x) {
        const int bn = tile * 128;
        for (int i = tid; i < 128 * 32; i += 256) {
            int row = i >> 5, c4 = (i & 31) * 4;
            int n = bn + row;
            float4 v = make_float4(0.f, 0.f, 0.f, 0.f);
            if (n < NN) v = *(const float4*)&g_h1[(size_t)n * 128 + c4];
            *(float4*)&sA[row * 132 + c4] = v;
        }
        __syncthreads();

        float acc[2][8][4];
#pragma unroll
        for (int mi = 0; mi < 2; ++mi)
#pragma unroll
            for (int ni = 0; ni < 8; ++ni) {
                int c = wc * 64 + ni * 8 + t2;
                acc[mi][ni][0] = sB[c]; acc[mi][ni][1] = sB[c + 1];
                acc[mi][ni][2] = sB[c]; acc[mi][ni][3] = sB[c + 1];
            }
        gemm_mma<132, 136, false>(sA, sW, 16, acc, wr, wc, lane);

#pragma unroll
        for (int mi = 0; mi < 2; ++mi) {
            int r = bn + wr * 32 + mi * 16 + g;
#pragma unroll
            for (int ni = 0; ni < 8; ++ni) {
                int c = wc * 64 + ni * 8 + t2;
                if (r < NN)
                    *(float2*)&outh[(size_t)r * 128 + c] =
                        make_float2(acc[mi][ni][0], acc[mi][ni][1]);
                if (r + 8 < NN)
                    *(float2*)&outh[(size_t)(r + 8) * 128 + c] =
                        make_float2(acc[mi][ni][2], acc[mi][ni][3]);
            }
        }
        __syncthreads();
    }
}

// ---------------- k_x / k_fin / k_norm ----------------
__global__ void k_x(const float* __restrict__ coord, float* __restrict__ outx) {
    __shared__ float sred[6];
    int tid = threadIdx.x;
    if (tid < 6) sred[tid] = 0.f;
    __syncthreads();
    float ls[6] = {0.f, 0.f, 0.f, 0.f, 0.f, 0.f};
    int stride = gridDim.x * blockDim.x;
    for (int n = blockIdx.x * blockDim.x + tid; n < NN; n += stride) {
        float deg = fmaxf(g_deg[n], 1.0f);
        float invd = 1.0f / deg;
#pragma unroll
        for (int d = 0; d < 3; ++d) {
            float x = coord[n * 3 + d] + g_xsum[n * 3 + d] * invd;
            outx[n * 3 + d] = x;
            ls[d] += x;
            ls[3 + d] += x * x;
        }
    }
#pragma unroll
    for (int k = 0; k < 6; ++k) atomicAdd(&sred[k], ls[k]);
    __syncthreads();
    if (tid < 6) atomicAdd(&g_red[tid], sred[tid]);
}

__global__ void k_fin() {
    int t = threadIdx.x;
    if (t < 3) {
        float mean = g_red[t] / (float)NN;
        float m2   = g_red[3 + t] / (float)NN;
        float var  = m2 - mean * mean;
        g_red[8 + t]  = mean;
        g_red[11 + t] = 1.0f / (sqrtf(var + 1e-6f) + 1e-6f);
    }
}

__global__ void k_norm(float* __restrict__ outx) {
    int stride = gridDim.x * blockDim.x;
    for (int i = blockIdx.x * blockDim.x + threadIdx.x; i < NN * 3; i += stride) {
        int d = i % 3;
        outx[i] = (outx[i] - g_red[8 + d]) * g_red[11 + d];
    }
}

// ---------------- launch ----------------
extern "C" void kernel_launch(void* const* d_in, const int* in_sizes, int n_in,
                              void* d_out, int out_size) {
    const float* nf    = (const float*)d_in[0];
    const float* coord = (const float*)d_in[1];
    const int*   src   = (const int*)d_in[2];
    const int*   dst   = (const int*)d_in[3];
    const float* W1 = (const float*)d_in[4];
    const float* b1 = (const float*)d_in[5];
    const float* W2 = (const float*)d_in[6];
    const float* b2 = (const float*)d_in[7];
    const float* W3 = (const float*)d_in[8];
    const float* b3 = (const float*)d_in[9];
    const float* W4 = (const float*)d_in[10];
    const float* b4 = (const float*)d_in[11];
    const float* W5 = (const float*)d_in[12];
    const float* b5 = (const float*)d_in[13];
    const float* W6 = (const float*)d_in[14];

    float* outh = (float*)d_out;
    float* outx = outh + (size_t)NN * C;

    const int SM_E1 = (16384 + 17408 + 17920 + 128) * 4 + 2 * 128 * 4;
    const int SM_E2 = (16384 + 16384 + 16896 + 128) * 4 + 2 * 128 * 4;
    const int SM_N1 = (128 * 136 * 2 + 128 * 132 + 128) * 4;
    const int SM_N2 = (128 * 136 + 128 * 132 + 128) * 4;

    cudaFuncSetAttribute(k_edge1, cudaFuncAttributeMaxDynamicSharedMemorySize, SM_E1);
    cudaFuncSetAttribute(k_edge2, cudaFuncAttributeMaxDynamicSharedMemorySize, SM_E2);
    cudaFuncSetAttribute(k_node1, cudaFuncAttributeMaxDynamicSharedMemorySize, SM_N1);
    cudaFuncSetAttribute(k_node2, cudaFuncAttributeMaxDynamicSharedMemorySize, SM_N2);

    k_init<<<2048, 256>>>();
    k_edge1<<<148, 256, SM_E1>>>(nf, coord, src, dst, W1, b1);
    k_edge2<<<148, 256, SM_E2>>>(coord, src, dst, W2, b2, W5, b5, W6);
    k_node1<<<148, 256, SM_N1>>>(nf, W3, b3);
    k_node2<<<148, 256, SM_N2>>>(W4, b4, outh);
    k_x<<<160, 256>>>(coord, outx);
    k_fin<<<1, 32>>>();
    k_norm<<<160, 256>>>(outx);
}

// round 7
// speedup vs baseline: 4.4527x; 1.0888x over previous
#include <cuda_runtime.h>
#include <cuda_bf16.h>
#include <math.h>

#define NN 50000
#define NE 800000
#define C  128

// ---------------- device scratch ----------------
static __device__ float g_h1[(size_t)NE * C];    // edge hidden (paired layout) / node t1 reuse (row-major)
static __device__ float g_hneigh[(size_t)NN * C];
static __device__ float g_xsum[NN * 3];
static __device__ float g_deg[NN];
static __device__ float g_red[16];

__device__ __forceinline__ float silu_f(float v) {
    return v / (1.0f + __expf(-v));
}
__device__ __forceinline__ float tf32f(float x) {
    unsigned u;
    asm("cvt.rna.tf32.f32 %0, %1;" : "=r"(u) : "f"(x));
    return __uint_as_float(u);
}
__device__ __forceinline__ unsigned fu(float x) { return __float_as_uint(x); }

__device__ __forceinline__ void mma8(float* d, const unsigned* a, unsigned b0, unsigned b1) {
    asm volatile(
        "mma.sync.aligned.m16n8k8.row.col.f32.tf32.tf32.f32 "
        "{%0,%1,%2,%3}, {%4,%5,%6,%7}, {%8,%9}, {%0,%1,%2,%3};"
        : "+f"(d[0]), "+f"(d[1]), "+f"(d[2]), "+f"(d[3])
        : "r"(a[0]), "r"(a[1]), "r"(a[2]), "r"(a[3]), "r"(b0), "r"(b1));
}

__device__ __forceinline__ void cp16(float* dstS, const float* srcG) {
    unsigned s = (unsigned)__cvta_generic_to_shared(dstS);
    asm volatile("cp.async.ca.shared.global [%0], [%1], 16;" :: "r"(s), "l"(srcG));
}
__device__ __forceinline__ void cpwait() {
    asm volatile("cp.async.commit_group;\ncp.async.wait_group 0;" ::: "memory");
}

// =============== paired-k W layout ===============
// sWp[(kc*128 + c)*8 + 2*(k&3) + ((k>>2)&1)] holds W[k][c], kc = k>>3.
// B-fragment (k=t, k=t+4) for col c is one aligned float2.

// Generic warp-tile GEMM: A row-major in smem, B paired. NI = n-tiles of 8
// cols per warp (warp tile = 32 rows x NI*8 cols; col-warp base = wc*NI*8).
template<int SA, bool CVTA, int NI>
__device__ __forceinline__ void gemm_rApB(const float* __restrict__ sA,
                                          const float* __restrict__ sWp,
                                          int kchunks, float (&acc)[2][NI][4],
                                          int wr, int wc, int lane) {
    const int g = lane >> 2, t = lane & 3;
    const float* ar = sA + (wr * 32 + g) * SA + t;
    const float* bb = sWp + (wc * (NI * 8) + g) * 8 + 2 * t;
#pragma unroll 4
    for (int kc = 0; kc < kchunks; ++kc) {
        const float* ap = ar + kc * 8;
        float a00 = ap[0],       a01 = ap[8 * SA],       a02 = ap[4],       a03 = ap[8 * SA + 4];
        float a10 = ap[16 * SA], a11 = ap[24 * SA],      a12 = ap[16 * SA + 4], a13 = ap[24 * SA + 4];
        if (CVTA) {
            a00 = tf32f(a00); a01 = tf32f(a01); a02 = tf32f(a02); a03 = tf32f(a03);
            a10 = tf32f(a10); a11 = tf32f(a11); a12 = tf32f(a12); a13 = tf32f(a13);
        }
        unsigned A0[4] = {fu(a00), fu(a01), fu(a02), fu(a03)};
        unsigned A1[4] = {fu(a10), fu(a11), fu(a12), fu(a13)};
        const float* bp = bb + kc * 1024;
#pragma unroll
        for (int ni = 0; ni < NI; ++ni) {
            float2 b = *(const float2*)(bp + ni * 64);
            mma8(acc[0][ni], A0, fu(b.x), fu(b.y));
            mma8(acc[1][ni], A1, fu(b.x), fu(b.y));
        }
    }
}

// A paired layout direct from global (g_h1 tile), depth-1 register prefetch.
template<int NI>
__device__ __forceinline__ void gemm_gApB(const float* __restrict__ gA,
                                          const float* __restrict__ sWp,
                                          float (&acc)[2][NI][4],
                                          int wr, int wc, int lane) {
    const int g = lane >> 2, t = lane & 3;
    const float* ar = gA + (wr * 32 + g) * 128 + 2 * t;
    const float* bb = sWp + (wc * (NI * 8) + g) * 8 + 2 * t;
    float2 c0 = __ldg((const float2*)(ar));
    float2 c1 = __ldg((const float2*)(ar + 8 * 128));
    float2 c2 = __ldg((const float2*)(ar + 16 * 128));
    float2 c3 = __ldg((const float2*)(ar + 24 * 128));
#pragma unroll 4
    for (int kc = 0; kc < 16; ++kc) {
        float2 a0 = c0, a1 = c1, a2 = c2, a3 = c3;
        const float* nx = ar + ((kc + 1) & 15) * 8;
        c0 = __ldg((const float2*)(nx));
        c1 = __ldg((const float2*)(nx + 8 * 128));
        c2 = __ldg((const float2*)(nx + 16 * 128));
        c3 = __ldg((const float2*)(nx + 24 * 128));
        unsigned A0[4] = {fu(a0.x), fu(a1.x), fu(a0.y), fu(a1.y)};
        unsigned A1[4] = {fu(a2.x), fu(a3.x), fu(a2.y), fu(a3.y)};
        const float* bp = bb + kc * 1024;
#pragma unroll
        for (int ni = 0; ni < NI; ++ni) {
            float2 b = *(const float2*)(bp + ni * 64);
            mma8(acc[0][ni], A0, fu(b.x), fu(b.y));
            mma8(acc[1][ni], A1, fu(b.x), fu(b.y));
        }
    }
}

// Node-kernel GEMM (256 thr, 4x2 warp grid): A row-major, W padded row-major.
template<int SA, int SW, bool CVT>
__device__ __forceinline__ void gemm_mma(const float* __restrict__ sA,
                                         const float* __restrict__ sW,
                                         int kchunks, float (&acc)[2][8][4],
                                         int wr, int wc, int lane) {
    const int g = lane >> 2, t = lane & 3;
    const float* a0p = sA + (wr * 32 + g) * SA + t;
    const float* bB  = sW + t * SW + wc * 64 + g;
#pragma unroll 4
    for (int kc = 0; kc < kchunks; ++kc) {
        unsigned A0[4], A1[4];
        const float* ap = a0p + kc * 8;
        const float* ap1 = ap + 16 * SA;
        if (CVT) {
            A0[0] = fu(tf32f(ap[0]));      A0[1] = fu(tf32f(ap[8 * SA]));
            A0[2] = fu(tf32f(ap[4]));      A0[3] = fu(tf32f(ap[8 * SA + 4]));
            A1[0] = fu(tf32f(ap1[0]));     A1[1] = fu(tf32f(ap1[8 * SA]));
            A1[2] = fu(tf32f(ap1[4]));     A1[3] = fu(tf32f(ap1[8 * SA + 4]));
        } else {
            A0[0] = fu(ap[0]);      A0[1] = fu(ap[8 * SA]);
            A0[2] = fu(ap[4]);      A0[3] = fu(ap[8 * SA + 4]);
            A1[0] = fu(ap1[0]);     A1[1] = fu(ap1[8 * SA]);
            A1[2] = fu(ap1[4]);     A1[3] = fu(ap1[8 * SA + 4]);
        }
        const float* bp = bB + kc * 8 * SW;
#pragma unroll
        for (int ni = 0; ni < 8; ++ni) {
            unsigned b0 = fu(bp[ni * 8]);
            unsigned b1 = fu(bp[4 * SW + ni * 8]);
            mma8(acc[0][ni], A0, b0, b1);
            mma8(acc[1][ni], A1, b0, b1);
        }
    }
}

// ---------------- k_init ----------------
__global__ void k_init() {
    const long NC = (long)NN * C, N3 = NN * 3;
    const long TOT = NC + N3 + NN + 16;
    long stride = (long)gridDim.x * blockDim.x;
    for (long i = (long)blockIdx.x * blockDim.x + threadIdx.x; i < TOT; i += stride) {
        if (i < NC) g_hneigh[i] = 0.f;
        else if (i < NC + N3) g_xsum[i - NC] = 0.f;
        else if (i < NC + N3 + NN) g_deg[i - NC - N3] = 0.f;
        else g_red[i - NC - N3 - NN] = 0.f;
    }
}

// ---------------- k_edge1 (512 threads, 4x4 warp grid) ----------------
__global__ void __launch_bounds__(512, 1)
k_edge1(const float* __restrict__ nf, const float* __restrict__ coord,
        const int* __restrict__ src, const int* __restrict__ dst,
        const float* __restrict__ W1, const float* __restrict__ b1) {
    extern __shared__ float sm[];
    float* sWa = sm;                        // 16*128*8 = 16384
    float* sWb = sWa + 16384;               // 17*128*8 = 17408
    float* sA  = sWb + 17408;               // 128*140 = 17920
    float* sRad = sA + 17920;               // 128
    int* sSrc = (int*)(sRad + 128);         // 128
    int* sDst = sSrc + 128;                 // 128

    const int tid = threadIdx.x, lane = tid & 31, wid = tid >> 5;
    const int wr = wid & 3, wc = wid >> 2;   // wc 0..3
    const int g = lane >> 2, t = lane & 3;

    for (int i = tid; i < 17408; i += 512) sWb[i] = 0.f;
    __syncthreads();
    for (int i = tid; i < 128 * 128; i += 512) {
        int k = i >> 7, c = i & 127;
        int pos = ((k >> 3) * 128 + c) * 8 + 2 * (k & 3) + ((k >> 2) & 1);
        sWa[pos] = tf32f(W1[i]);
        sWb[pos] = tf32f(W1[128 * 128 + i]);
    }
    if (tid < 128) sWb[16384 + tid * 8] = tf32f(W1[256 * 128 + tid]);  // k=128 row
    __syncthreads();

    float blo[4], bhi[4];
    {
        int cb = wc * 32 + 2 * t;
#pragma unroll
        for (int ni = 0; ni < 4; ++ni) {
            blo[ni] = __ldg(&b1[cb + ni * 8]);
            bhi[ni] = __ldg(&b1[cb + ni * 8 + 1]);
        }
    }
    const int p0 = (t & 1) * 4 + (t >> 1);   // paired position of col offset 2t

    const int ntiles = NE / 128;
    for (int tile = blockIdx.x; tile < ntiles; tile += gridDim.x) {
        const int be = tile * 128;
        if (tid < 128) {
            int e = be + tid;
            int s = src[e], d = dst[e];
            sSrc[tid] = s; sDst[tid] = d;
            atomicAdd(&g_deg[d], 1.0f);
            float dx = coord[s * 3 + 0] - coord[d * 3 + 0];
            float dy = coord[s * 3 + 1] - coord[d * 3 + 1];
            float dz = coord[s * 3 + 2] - coord[d * 3 + 2];
            sRad[tid] = dx * dx + dy * dy + dz * dz;
        }
        __syncthreads();

        for (int i = tid; i < 4096; i += 512) {
            int row = i >> 5, c4 = (i & 31) * 4;
            cp16(&sA[row * 140 + c4], &nf[(size_t)sSrc[row] * 128 + c4]);
        }
        cpwait();
        __syncthreads();

        float acc[2][4][4];
#pragma unroll
        for (int mi = 0; mi < 2; ++mi)
#pragma unroll
            for (int ni = 0; ni < 4; ++ni) {
                acc[mi][ni][0] = blo[ni]; acc[mi][ni][1] = bhi[ni];
                acc[mi][ni][2] = blo[ni]; acc[mi][ni][3] = bhi[ni];
            }
        gemm_rApB<140, true, 4>(sA, sWa, 16, acc, wr, wc, lane);
        __syncthreads();

        for (int i = tid; i < 4096; i += 512) {
            int row = i >> 5, c4 = (i & 31) * 4;
            cp16(&sA[row * 140 + c4], &nf[(size_t)sDst[row] * 128 + c4]);
        }
        if (tid < 128) {
            float* p = &sA[tid * 140 + 128];
            *(float4*)p = make_float4(sRad[tid], 0.f, 0.f, 0.f);
            *(float4*)(p + 4) = make_float4(0.f, 0.f, 0.f, 0.f);
        }
        cpwait();
        __syncthreads();
        gemm_rApB<140, true, 4>(sA, sWb, 17, acc, wr, wc, lane);

        // epilogue: silu, tf32-round, store to g_h1 in PAIRED layout
#pragma unroll
        for (int mi = 0; mi < 2; ++mi) {
            size_t rb = (size_t)(be + wr * 32 + mi * 16 + g) * 128 + wc * 32;
#pragma unroll
            for (int ni = 0; ni < 4; ++ni) {
                size_t o = rb + ni * 8 + p0;
                g_h1[o]     = tf32f(silu_f(acc[mi][ni][0]));
                g_h1[o + 2] = tf32f(silu_f(acc[mi][ni][1]));
                g_h1[o + 8 * 128]     = tf32f(silu_f(acc[mi][ni][2]));
                g_h1[o + 8 * 128 + 2] = tf32f(silu_f(acc[mi][ni][3]));
            }
        }
    }
}

// ---------------- k_edge2 (512 threads, 4x4 warp grid) ----------------
__global__ void __launch_bounds__(512, 1)
k_edge2(const float* __restrict__ coord,
        const int* __restrict__ src, const int* __restrict__ dst,
        const float* __restrict__ W2, const float* __restrict__ b2,
        const float* __restrict__ W5, const float* __restrict__ b5,
        const float* __restrict__ W6) {
    extern __shared__ float sm[];
    float* sW2p = sm;                      // 16384
    float* sW5p = sW2p + 16384;            // 16384
    float* sH   = sW5p + 16384;            // 128*132 = 16896
    float* sCW  = sH + 16896;              // 128
    int* sSrc = (int*)(sCW + 128);         // 128
    int* sDst = sSrc + 128;                // 128

    const int tid = threadIdx.x, lane = tid & 31, wid = tid >> 5;
    const int wr = wid & 3, wc = wid >> 2;
    const int g = lane >> 2, t = lane & 3;

    for (int i = tid; i < 128 * 128; i += 512) {
        int k = i >> 7, c = i & 127;
        int pos = ((k >> 3) * 128 + c) * 8 + 2 * (k & 3) + ((k >> 2) & 1);
        sW2p[pos] = tf32f(W2[i]);
        sW5p[pos] = tf32f(W5[i]);
    }
    __syncthreads();

    float b2lo[4], b2hi[4], b5lo[4], b5hi[4], w6lo[4], w6hi[4];
    {
        int cb = wc * 32 + 2 * t;
#pragma unroll
        for (int ni = 0; ni < 4; ++ni) {
            b2lo[ni] = __ldg(&b2[cb + ni * 8]); b2hi[ni] = __ldg(&b2[cb + ni * 8 + 1]);
            b5lo[ni] = __ldg(&b5[cb + ni * 8]); b5hi[ni] = __ldg(&b5[cb + ni * 8 + 1]);
            w6lo[ni] = __ldg(&W6[cb + ni * 8]); w6hi[ni] = __ldg(&W6[cb + ni * 8 + 1]);
        }
    }

    const int ntiles = NE / 128;
    for (int tile = blockIdx.x; tile < ntiles; tile += gridDim.x) {
        const int be = tile * 128;
        if (tid < 128) {
            sSrc[tid] = src[be + tid];
            sDst[tid] = dst[be + tid];
            sCW[tid] = 0.f;
        }

        float acc[2][4][4];
#pragma unroll
        for (int mi = 0; mi < 2; ++mi)
#pragma unroll
            for (int ni = 0; ni < 4; ++ni) {
                acc[mi][ni][0] = b2lo[ni]; acc[mi][ni][1] = b2hi[ni];
                acc[mi][ni][2] = b2lo[ni]; acc[mi][ni][3] = b2hi[ni];
            }
        gemm_gApB<4>(g_h1 + (size_t)tile * 16384, sW2p, acc, wr, wc, lane);

#pragma unroll
        for (int mi = 0; mi < 2; ++mi) {
            int r = wr * 32 + mi * 16 + g;
#pragma unroll
            for (int ni = 0; ni < 4; ++ni) {
                int c = wc * 32 + ni * 8 + 2 * t;
                *(float2*)&sH[r * 132 + c] =
                    make_float2(silu_f(acc[mi][ni][0]), silu_f(acc[mi][ni][1]));
                *(float2*)&sH[(r + 8) * 132 + c] =
                    make_float2(silu_f(acc[mi][ni][2]), silu_f(acc[mi][ni][3]));
            }
        }
        __syncthreads();   // (1) h2 + indices ready

        float acc2[2][4][4];
#pragma unroll
        for (int mi = 0; mi < 2; ++mi)
#pragma unroll
            for (int ni = 0; ni < 4; ++ni) {
                acc2[mi][ni][0] = b5lo[ni]; acc2[mi][ni][1] = b5hi[ni];
                acc2[mi][ni][2] = b5lo[ni]; acc2[mi][ni][3] = b5hi[ni];
            }
        gemm_rApB<132, true, 4>(sH, sW5p, 16, acc2, wr, wc, lane);

        // scatter h2 -> g_hneigh (vector reduction atomics)
        for (int i = tid; i < 4096; i += 512) {
            int row = i >> 5, c4 = (i & 31) * 4;
            const float4 v = *(const float4*)&sH[row * 132 + c4];
            float* p = &g_hneigh[(size_t)sDst[row] * 128 + c4];
            asm volatile("red.global.add.v4.f32 [%0], {%1,%2,%3,%4};"
                         :: "l"(p), "f"(v.x), "f"(v.y), "f"(v.z), "f"(v.w) : "memory");
        }

        // dot: cw[row] = sum_c silu(h3pre)*W6[c]
#pragma unroll
        for (int mi = 0; mi < 2; ++mi) {
            float pr0 = 0.f, pr1 = 0.f;
#pragma unroll
            for (int ni = 0; ni < 4; ++ni) {
                pr0 += silu_f(acc2[mi][ni][0]) * w6lo[ni] + silu_f(acc2[mi][ni][1]) * w6hi[ni];
                pr1 += silu_f(acc2[mi][ni][2]) * w6lo[ni] + silu_f(acc2[mi][ni][3]) * w6hi[ni];
            }
            pr0 += __shfl_xor_sync(0xffffffffu, pr0, 1);
            pr0 += __shfl_xor_sync(0xffffffffu, pr0, 2);
            pr1 += __shfl_xor_sync(0xffffffffu, pr1, 1);
            pr1 += __shfl_xor_sync(0xffffffffu, pr1, 2);
            if (t == 0) {
                int r = wr * 32 + mi * 16 + g;
                atomicAdd(&sCW[r], pr0);
                atomicAdd(&sCW[r + 8], pr1);
            }
        }
        __syncthreads();   // (2) sCW complete, scatter reads of sH done

        if (tid < 128) {
            int s = sSrc[tid], d = sDst[tid];
            float dx = coord[s * 3 + 0] - coord[d * 3 + 0];
            float dy = coord[s * 3 + 1] - coord[d * 3 + 1];
            float dz = coord[s * 3 + 2] - coord[d * 3 + 2];
            float r  = dx * dx + dy * dy + dz * dz;
            float inv = 1.0f / (sqrtf(r + 1e-6f) + 1e-6f);
            float cws = sCW[tid] * inv;
            atomicAdd(&g_xsum[d * 3 + 0], cws * dx);
            atomicAdd(&g_xsum[d * 3 + 1], cws * dy);
            atomicAdd(&g_xsum[d * 3 + 2], cws * dz);
        }
        __syncthreads();   // (3) protect sCW/sH for next tile
    }
}

// ---------------- k_node1 (256 threads) ----------------
__global__ void __launch_bounds__(256, 1)
k_node1(const float* __restrict__ nf, const float* __restrict__ W3,
        const float* __restrict__ b3) {
    extern __shared__ float sm[];
    float* sWa = sm;                       // 128*136
    float* sWb = sWa + 128 * 136;          // 128*136
    float* sA  = sWb + 128 * 136;          // 128*132
    float* sB  = sA + 128 * 132;           // 128

    const int tid = threadIdx.x, lane = tid & 31, wid = tid >> 5;
    const int wr = wid & 3, wc = wid >> 2;
    const int g = lane >> 2, t2 = 2 * (lane & 3);

    for (int i = tid; i < 128 * 128; i += 256) {
        int k = i >> 7, n = i & 127;
        sWa[k * 136 + n] = tf32f(W3[i]);
        sWb[k * 136 + n] = tf32f(W3[128 * 128 + i]);
    }
    if (tid < 128) sB[tid] = b3[tid];
    __syncthreads();

    const int ntiles = (NN + 127) / 128;
    for (int tile = blockIdx.x; tile < ntiles; tile += gridDim.x) {
        const int bn = tile * 128;
        for (int i = tid; i < 128 * 32; i += 256) {
            int row = i >> 5, c4 = (i & 31) * 4;
            int n = bn + row;
            float4 v = make_float4(0.f, 0.f, 0.f, 0.f);
            if (n < NN) v = *(const float4*)&nf[(size_t)n * 128 + c4];
            float* p = &sA[row * 132 + c4];
            p[0] = tf32f(v.x); p[1] = tf32f(v.y); p[2] = tf32f(v.z); p[3] = tf32f(v.w);
        }
        __syncthreads();

        float acc[2][8][4];
#pragma unroll
        for (int mi = 0; mi < 2; ++mi)
#pragma unroll
            for (int ni = 0; ni < 8; ++ni) {
                int c = wc * 64 + ni * 8 + t2;
                acc[mi][ni][0] = sB[c]; acc[mi][ni][1] = sB[c + 1];
                acc[mi][ni][2] = sB[c]; acc[mi][ni][3] = sB[c + 1];
            }
        gemm_mma<132, 136, false>(sA, sWa, 16, acc, wr, wc, lane);
        __syncthreads();
        for (int i = tid; i < 128 * 32; i += 256) {
            int row = i >> 5, c4 = (i & 31) * 4;
            int n = bn + row;
            float4 v = make_float4(0.f, 0.f, 0.f, 0.f);
            if (n < NN) v = *(const float4*)&g_hneigh[(size_t)n * 128 + c4];
            float* p = &sA[row * 132 + c4];
            p[0] = tf32f(v.x); p[1] = tf32f(v.y); p[2] = tf32f(v.z); p[3] = tf32f(v.w);
        }
        __syncthreads();
        gemm_mma<132, 136, false>(sA, sWb, 16, acc, wr, wc, lane);

#pragma unroll
        for (int mi = 0; mi < 2; ++mi) {
            int r = bn + wr * 32 + mi * 16 + g;
#pragma unroll
            for (int ni = 0; ni < 8; ++ni) {
                int c = wc * 64 + ni * 8 + t2;
                if (r < NN)
                    *(float2*)&g_h1[(size_t)r * 128 + c] =
                        make_float2(tf32f(silu_f(acc[mi][ni][0])), tf32f(silu_f(acc[mi][ni][1])));
                if (r + 8 < NN)
                    *(float2*)&g_h1[(size_t)(r + 8) * 128 + c] =
                        make_float2(tf32f(silu_f(acc[mi][ni][2])), tf32f(silu_f(acc[mi][ni][3])));
            }
        }
        __syncthreads();
    }
}

// ---------------- k_node2 (256 threads) ----------------
__global__ void __launch_bounds__(256, 1)
k_node2(const float* __restrict__ W4, const float* __restrict__ b4,
        float* __restrict__ outh) {
    extern __shared__ float sm[];
    float* sW = sm;                        // 128*136
    float* sA = sW + 128 * 136;            // 128*132
    float* sB = sA + 128 * 132;            // 128

    const int tid = threadIdx.x, lane = tid & 31, wid = tid >> 5;
    const int wr = wid & 3, wc = wid >> 2;
    const int g = lane >> 2, t2 = 2 * (lane & 3);

    for (int i = tid; i < 128 * 128; i += 256) {
        int k = i >> 7, n = i & 127;
        sW[k * 136 + n] = tf32f(W4[i]);
    }
    if (tid < 128) sB[tid] = b4[tid];
    __syncthreads();

    const int ntiles = (NN + 127) / 128;
    for (int tile = blockIdx.x; tile < ntiles; tile += gridDim.x) {
        const int bn = tile * 128;
        for (int i = tid; i < 128 * 32; i += 256) {
            int row = i >> 5, c4 = (i & 31) * 4;
            int n = bn + row;
            float4 v = make_float4(0.f, 0.f, 0.f, 0.f);
            if (n < NN) v = *(const float4*)&g_h1[(size_t)n * 128 + c4];
            *(float4*)&sA[row * 132 + c4] = v;
        }
        __syncthreads();

        float acc[2][8][4];
#pragma unroll
        for (int mi = 0; mi < 2; ++mi)
#pragma unroll
            for (int ni = 0; ni < 8; ++ni) {
                int c = wc * 64 + ni * 8 + t2;
                acc[mi][ni][0] = sB[c]; acc[mi][ni][1] = sB[c + 1];
                acc[mi][ni][2] = sB[c]; acc[mi][ni][3] = sB[c + 1];
            }
        gemm_mma<132, 136, false>(sA, sW, 16, acc, wr, wc, lane);

#pragma unroll
        for (int mi = 0; mi < 2; ++mi) {
            int r = bn + wr * 32 + mi * 16 + g;
#pragma unroll
            for (int ni = 0; ni < 8; ++ni) {
                int c = wc * 64 + ni * 8 + t2;
                if (r < NN)
                    *(float2*)&outh[(size_t)r * 128 + c] =
                        make_float2(acc[mi][ni][0], acc[mi][ni][1]);
                if (r + 8 < NN)
                    *(float2*)&outh[(size_t)(r + 8) * 128 + c] =
                        make_float2(acc[mi][ni][2], acc[mi][ni][3]);
            }
        }
        __syncthreads();
    }
}

// ---------------- k_x / k_fin / k_norm ----------------
__global__ void k_x(const float* __restrict__ coord, float* __restrict__ outx) {
    __shared__ float sred[6];
    int tid = threadIdx.x;
    if (tid < 6) sred[tid] = 0.f;
    __syncthreads();
    float ls[6] = {0.f, 0.f, 0.f, 0.f, 0.f, 0.f};
    int stride = gridDim.x * blockDim.x;
    for (int n = blockIdx.x * blockDim.x + tid; n < NN; n += stride) {
        float deg = fmaxf(g_deg[n], 1.0f);
        float invd = 1.0f / deg;
#pragma unroll
        for (int d = 0; d < 3; ++d) {
            float x = coord[n * 3 + d] + g_xsum[n * 3 + d] * invd;
            outx[n * 3 + d] = x;
            ls[d] += x;
            ls[3 + d] += x * x;
        }
    }
#pragma unroll
    for (int k = 0; k < 6; ++k) atomicAdd(&sred[k], ls[k]);
    __syncthreads();
    if (tid < 6) atomicAdd(&g_red[tid], sred[tid]);
}

__global__ void k_fin() {
    int t = threadIdx.x;
    if (t < 3) {
        float mean = g_red[t] / (float)NN;
        float m2   = g_red[3 + t] / (float)NN;
        float var  = m2 - mean * mean;
        g_red[8 + t]  = mean;
        g_red[11 + t] = 1.0f / (sqrtf(var + 1e-6f) + 1e-6f);
    }
}

__global__ void k_norm(float* __restrict__ outx) {
    int stride = gridDim.x * blockDim.x;
    for (int i = blockIdx.x * blockDim.x + threadIdx.x; i < NN * 3; i += stride) {
        int d = i % 3;
        outx[i] = (outx[i] - g_red[8 + d]) * g_red[11 + d];
    }
}

// ---------------- launch ----------------
extern "C" void kernel_launch(void* const* d_in, const int* in_sizes, int n_in,
                              void* d_out, int out_size) {
    const float* nf    = (const float*)d_in[0];
    const float* coord = (const float*)d_in[1];
    const int*   src   = (const int*)d_in[2];
    const int*   dst   = (const int*)d_in[3];
    const float* W1 = (const float*)d_in[4];
    const float* b1 = (const float*)d_in[5];
    const float* W2 = (const float*)d_in[6];
    const float* b2 = (const float*)d_in[7];
    const float* W3 = (const float*)d_in[8];
    const float* b3 = (const float*)d_in[9];
    const float* W4 = (const float*)d_in[10];
    const float* b4 = (const float*)d_in[11];
    const float* W5 = (const float*)d_in[12];
    const float* b5 = (const float*)d_in[13];
    const float* W6 = (const float*)d_in[14];

    float* outh = (float*)d_out;
    float* outx = outh + (size_t)NN * C;

    const int SM_E1 = (16384 + 17408 + 17920 + 128) * 4 + 2 * 128 * 4;
    const int SM_E2 = (16384 + 16384 + 16896 + 128) * 4 + 2 * 128 * 4;
    const int SM_N1 = (128 * 136 * 2 + 128 * 132 + 128) * 4;
    const int SM_N2 = (128 * 136 + 128 * 132 + 128) * 4;

    cudaFuncSetAttribute(k_edge1, cudaFuncAttributeMaxDynamicSharedMemorySize, SM_E1);
    cudaFuncSetAttribute(k_edge2, cudaFuncAttributeMaxDynamicSharedMemorySize, SM_E2);
    cudaFuncSetAttribute(k_node1, cudaFuncAttributeMaxDynamicSharedMemorySize, SM_N1);
    cudaFuncSetAttribute(k_node2, cudaFuncAttributeMaxDynamicSharedMemorySize, SM_N2);

    k_init<<<2048, 256>>>();
    k_edge1<<<148, 512, SM_E1>>>(nf, coord, src, dst, W1, b1);
    k_edge2<<<148, 512, SM_E2>>>(coord, src, dst, W2, b2, W5, b5, W6);
    k_node1<<<148, 256, SM_N1>>>(nf, W3, b3);
    k_node2<<<148, 256, SM_N2>>>(W4, b4, outh);
    k_x<<<160, 256>>>(coord, outx);
    k_fin<<<1, 32>>>();
    k_norm<<<160, 256>>>(outx);
}

// round 9
// speedup vs baseline: 6.3768x; 1.4321x over previous
#include <cuda_runtime.h>
#include <cuda_bf16.h>
#include <math.h>

#define NN 50000
#define NE 800000
#define C  128

// ---------------- device scratch ----------------
static __device__ float g_P1[(size_t)NN * C];    // nf @ W1a
static __device__ float g_P2[(size_t)NN * C];    // nf @ W1b
static __device__ float g_t1[(size_t)NN * C];    // node hidden
static __device__ float g_hneigh[(size_t)NN * C];
static __device__ float g_xsum[NN * 3];
static __device__ float g_deg[NN];
static __device__ float g_red[16];

__device__ __forceinline__ float silu_f(float v) {
    return v / (1.0f + __expf(-v));
}
__device__ __forceinline__ float tf32f(float x) {
    unsigned u;
    asm("cvt.rna.tf32.f32 %0, %1;" : "=r"(u) : "f"(x));
    return __uint_as_float(u);
}
__device__ __forceinline__ unsigned fu(float x) { return __float_as_uint(x); }

__device__ __forceinline__ void mma8(float* d, const unsigned* a, unsigned b0, unsigned b1) {
    asm volatile(
        "mma.sync.aligned.m16n8k8.row.col.f32.tf32.tf32.f32 "
        "{%0,%1,%2,%3}, {%4,%5,%6,%7}, {%8,%9}, {%0,%1,%2,%3};"
        : "+f"(d[0]), "+f"(d[1]), "+f"(d[2]), "+f"(d[3])
        : "r"(a[0]), "r"(a[1]), "r"(a[2]), "r"(a[3]), "r"(b0), "r"(b1));
}

// =============== paired-k W layout ===============
// sWp[(kc*128 + c)*8 + 2*(k&3) + ((k>>2)&1)] holds W[k][c], kc = k>>3.
// B-fragment (k=t, k=t+4) for col c is one aligned float2.

// Warp-tile GEMM: A row-major in smem (optional tf32 cvt), B paired.
// 512 threads: warp grid 4(row) x 4(col), warp tile 32 rows x 32 cols (NI=4).
template<int SA, bool CVTA, int NI>
__device__ __forceinline__ void gemm_rApB(const float* __restrict__ sA,
                                          const float* __restrict__ sWp,
                                          int kchunks, float (&acc)[2][NI][4],
                                          int wr, int wc, int lane) {
    const int g = lane >> 2, t = lane & 3;
    const float* ar = sA + (wr * 32 + g) * SA + t;
    const float* bb = sWp + (wc * (NI * 8) + g) * 8 + 2 * t;
#pragma unroll 4
    for (int kc = 0; kc < kchunks; ++kc) {
        const float* ap = ar + kc * 8;
        float a00 = ap[0],       a01 = ap[8 * SA],       a02 = ap[4],       a03 = ap[8 * SA + 4];
        float a10 = ap[16 * SA], a11 = ap[24 * SA],      a12 = ap[16 * SA + 4], a13 = ap[24 * SA + 4];
        if (CVTA) {
            a00 = tf32f(a00); a01 = tf32f(a01); a02 = tf32f(a02); a03 = tf32f(a03);
            a10 = tf32f(a10); a11 = tf32f(a11); a12 = tf32f(a12); a13 = tf32f(a13);
        }
        unsigned A0[4] = {fu(a00), fu(a01), fu(a02), fu(a03)};
        unsigned A1[4] = {fu(a10), fu(a11), fu(a12), fu(a13)};
        const float* bp = bb + kc * 1024;
#pragma unroll
        for (int ni = 0; ni < NI; ++ni) {
            float2 b = *(const float2*)(bp + ni * 64);
            mma8(acc[0][ni], A0, fu(b.x), fu(b.y));
            mma8(acc[1][ni], A1, fu(b.x), fu(b.y));
        }
    }
}

// load W[16384] (row-major [128][128]) into paired layout with tf32 rounding
__device__ __forceinline__ void load_paired(float* sWp, const float* W, int tid, int nthr) {
    for (int i = tid; i < 16384; i += nthr) {
        int k = i >> 7, c = i & 127;
        int pos = ((k >> 3) * 128 + c) * 8 + 2 * (k & 3) + ((k >> 2) & 1);
        sWp[pos] = tf32f(W[i]);
    }
}

// ---------------- k_init ----------------
__global__ void k_init() {
    const long NC = (long)NN * C, N3 = NN * 3;
    const long TOT = NC + N3 + NN + 16;
    long stride = (long)gridDim.x * blockDim.x;
    for (long i = (long)blockIdx.x * blockDim.x + threadIdx.x; i < TOT; i += stride) {
        if (i < NC) g_hneigh[i] = 0.f;
        else if (i < NC + N3) g_xsum[i - NC] = 0.f;
        else if (i < NC + N3 + NN) g_deg[i - NC - N3] = 0.f;
        else g_red[i - NC - N3 - NN] = 0.f;
    }
}

// ---------------- k_npre: P1 = nf@W1a, P2 = nf@W1b ----------------
__global__ void __launch_bounds__(512, 1)
k_npre(const float* __restrict__ nf, const float* __restrict__ W1) {
    extern __shared__ float sm[];
    float* sWa = sm;                       // 16384 (paired)
    float* sWb = sWa + 16384;              // 16384 (paired)
    float* sA  = sWb + 16384;              // 128*132 = 16896

    const int tid = threadIdx.x, lane = tid & 31, wid = tid >> 5;
    const int wr = wid & 3, wc = wid >> 2;
    const int g = lane >> 2, t = lane & 3;

    load_paired(sWa, W1, tid, 512);
    load_paired(sWb, W1 + 16384, tid, 512);
    __syncthreads();

    const int ntiles = (NN + 127) / 128;
    for (int tile = blockIdx.x; tile < ntiles; tile += gridDim.x) {
        const int bn = tile * 128;
        for (int i = tid; i < 4096; i += 512) {
            int row = i >> 5, c4 = (i & 31) * 4;
            int n = bn + row;
            float4 v = make_float4(0.f, 0.f, 0.f, 0.f);
            if (n < NN) v = *(const float4*)&nf[(size_t)n * 128 + c4];
            float* p = &sA[row * 132 + c4];
            p[0] = tf32f(v.x); p[1] = tf32f(v.y); p[2] = tf32f(v.z); p[3] = tf32f(v.w);
        }
        __syncthreads();

        float acc[2][4][4];
#pragma unroll
        for (int mi = 0; mi < 2; ++mi)
#pragma unroll
            for (int ni = 0; ni < 4; ++ni)
#pragma unroll
                for (int q = 0; q < 4; ++q) acc[mi][ni][q] = 0.f;
        gemm_rApB<132, false, 4>(sA, sWa, 16, acc, wr, wc, lane);
#pragma unroll
        for (int mi = 0; mi < 2; ++mi) {
            int r = bn + wr * 32 + mi * 16 + g;
#pragma unroll
            for (int ni = 0; ni < 4; ++ni) {
                int c = wc * 32 + ni * 8 + 2 * t;
                if (r < NN)
                    *(float2*)&g_P1[(size_t)r * 128 + c] = make_float2(acc[mi][ni][0], acc[mi][ni][1]);
                if (r + 8 < NN)
                    *(float2*)&g_P1[(size_t)(r + 8) * 128 + c] = make_float2(acc[mi][ni][2], acc[mi][ni][3]);
            }
        }
#pragma unroll
        for (int mi = 0; mi < 2; ++mi)
#pragma unroll
            for (int ni = 0; ni < 4; ++ni)
#pragma unroll
                for (int q = 0; q < 4; ++q) acc[mi][ni][q] = 0.f;
        gemm_rApB<132, false, 4>(sA, sWb, 16, acc, wr, wc, lane);
#pragma unroll
        for (int mi = 0; mi < 2; ++mi) {
            int r = bn + wr * 32 + mi * 16 + g;
#pragma unroll
            for (int ni = 0; ni < 4; ++ni) {
                int c = wc * 32 + ni * 8 + 2 * t;
                if (r < NN)
                    *(float2*)&g_P2[(size_t)r * 128 + c] = make_float2(acc[mi][ni][0], acc[mi][ni][1]);
                if (r + 8 < NN)
                    *(float2*)&g_P2[(size_t)(r + 8) * 128 + c] = make_float2(acc[mi][ni][2], acc[mi][ni][3]);
            }
        }
        __syncthreads();
    }
}

// ---------------- k_edge: fused edge pipeline ----------------
// h1 = silu(P1[s]+P2[d]+r*wr+b1); h2 = silu(h1@W2+b2) -> scatter;
// cw = silu(h2@W5+b5).W6 -> coord scatter.
__global__ void __launch_bounds__(512, 1)
k_edge(const float* __restrict__ coord,
       const int* __restrict__ src, const int* __restrict__ dst,
       const float* __restrict__ W1, const float* __restrict__ b1,
       const float* __restrict__ W2, const float* __restrict__ b2,
       const float* __restrict__ W5, const float* __restrict__ b5,
       const float* __restrict__ W6) {
    extern __shared__ float sm[];
    float* sW2p = sm;                      // 16384 (paired)
    float* sW5p = sW2p + 16384;            // 16384 (paired)
    float* sA   = sW5p + 16384;            // 128*132 = 16896
    float* sWr  = sA + 16896;              // 128
    float* sB1  = sWr + 128;               // 128
    float* sRad = sB1 + 128;               // 128
    float* sCW  = sRad + 128;              // 128
    int* sSrc = (int*)(sCW + 128);         // 128
    int* sDst = sSrc + 128;                // 128

    const int tid = threadIdx.x, lane = tid & 31, wid = tid >> 5;
    const int wr = wid & 3, wc = wid >> 2;
    const int g = lane >> 2, t = lane & 3;

    load_paired(sW2p, W2, tid, 512);
    load_paired(sW5p, W5, tid, 512);
    if (tid < 128) { sWr[tid] = W1[256 * 128 + tid]; sB1[tid] = b1[tid]; }
    __syncthreads();

    float b2lo[4], b2hi[4], b5lo[4], b5hi[4], w6lo[4], w6hi[4];
    {
        int cb = wc * 32 + 2 * t;
#pragma unroll
        for (int ni = 0; ni < 4; ++ni) {
            b2lo[ni] = __ldg(&b2[cb + ni * 8]); b2hi[ni] = __ldg(&b2[cb + ni * 8 + 1]);
            b5lo[ni] = __ldg(&b5[cb + ni * 8]); b5hi[ni] = __ldg(&b5[cb + ni * 8 + 1]);
            w6lo[ni] = __ldg(&W6[cb + ni * 8]); w6hi[ni] = __ldg(&W6[cb + ni * 8 + 1]);
        }
    }

    const int ntiles = NE / 128;
    for (int tile = blockIdx.x; tile < ntiles; tile += gridDim.x) {
        const int be = tile * 128;
        if (tid < 128) {
            int e = be + tid;
            int s = src[e], d = dst[e];
            sSrc[tid] = s; sDst[tid] = d; sCW[tid] = 0.f;
            atomicAdd(&g_deg[d], 1.0f);
            float dx = coord[s * 3 + 0] - coord[d * 3 + 0];
            float dy = coord[s * 3 + 1] - coord[d * 3 + 1];
            float dz = coord[s * 3 + 2] - coord[d * 3 + 2];
            sRad[tid] = dx * dx + dy * dy + dz * dz;
        }
        __syncthreads();   // (1) indices/radial ready; prior-tile readers done

        // gather-assemble h1 into sA (tf32-rounded)
        for (int i = tid; i < 4096; i += 512) {
            int row = i >> 5, c4 = (i & 31) * 4;
            const float4 p1 = *(const float4*)&g_P1[(size_t)sSrc[row] * 128 + c4];
            const float4 p2 = *(const float4*)&g_P2[(size_t)sDst[row] * 128 + c4];
            const float4 w4 = *(const float4*)&sWr[c4];
            const float4 bb = *(const float4*)&sB1[c4];
            float r = sRad[row];
            float4 o;
            o.x = tf32f(silu_f(p1.x + p2.x + r * w4.x + bb.x));
            o.y = tf32f(silu_f(p1.y + p2.y + r * w4.y + bb.y));
            o.z = tf32f(silu_f(p1.z + p2.z + r * w4.z + bb.z));
            o.w = tf32f(silu_f(p1.w + p2.w + r * w4.w + bb.w));
            *(float4*)&sA[row * 132 + c4] = o;
        }
        __syncthreads();   // (2) h1 complete

        // GEMM1: h2pre = h1 @ W2 + b2
        float acc[2][4][4];
#pragma unroll
        for (int mi = 0; mi < 2; ++mi)
#pragma unroll
            for (int ni = 0; ni < 4; ++ni) {
                acc[mi][ni][0] = b2lo[ni]; acc[mi][ni][1] = b2hi[ni];
                acc[mi][ni][2] = b2lo[ni]; acc[mi][ni][3] = b2hi[ni];
            }
        gemm_rApB<132, false, 4>(sA, sW2p, 16, acc, wr, wc, lane);
        __syncthreads();   // (3) all h1 reads done

        // write h2 = silu(acc) (fp32) into sA (own 32x32 block)
#pragma unroll
        for (int mi = 0; mi < 2; ++mi) {
            int r = wr * 32 + mi * 16 + g;
#pragma unroll
            for (int ni = 0; ni < 4; ++ni) {
                int c = wc * 32 + ni * 8 + 2 * t;
                *(float2*)&sA[r * 132 + c] =
                    make_float2(silu_f(acc[mi][ni][0]), silu_f(acc[mi][ni][1]));
                *(float2*)&sA[(r + 8) * 132 + c] =
                    make_float2(silu_f(acc[mi][ni][2]), silu_f(acc[mi][ni][3]));
            }
        }
        __syncthreads();   // (4) h2 complete

        // GEMM2: h3pre = h2 @ W5 + b5 (cvt A)
        float acc2[2][4][4];
#pragma unroll
        for (int mi = 0; mi < 2; ++mi)
#pragma unroll
            for (int ni = 0; ni < 4; ++ni) {
                acc2[mi][ni][0] = b5lo[ni]; acc2[mi][ni][1] = b5hi[ni];
                acc2[mi][ni][2] = b5lo[ni]; acc2[mi][ni][3] = b5hi[ni];
            }
        gemm_rApB<132, true, 4>(sA, sW5p, 16, acc2, wr, wc, lane);

        // scatter h2 -> g_hneigh (vector reduction atomics)
        for (int i = tid; i < 4096; i += 512) {
            int row = i >> 5, c4 = (i & 31) * 4;
            const float4 v = *(const float4*)&sA[row * 132 + c4];
            float* p = &g_hneigh[(size_t)sDst[row] * 128 + c4];
            asm volatile("red.global.add.v4.f32 [%0], {%1,%2,%3,%4};"
                         :: "l"(p), "f"(v.x), "f"(v.y), "f"(v.z), "f"(v.w) : "memory");
        }

        // cw[row] = sum_c silu(h3pre)*W6[c]
#pragma unroll
        for (int mi = 0; mi < 2; ++mi) {
            float pr0 = 0.f, pr1 = 0.f;
#pragma unroll
            for (int ni = 0; ni < 4; ++ni) {
                pr0 += silu_f(acc2[mi][ni][0]) * w6lo[ni] + silu_f(acc2[mi][ni][1]) * w6hi[ni];
                pr1 += silu_f(acc2[mi][ni][2]) * w6lo[ni] + silu_f(acc2[mi][ni][3]) * w6hi[ni];
            }
            pr0 += __shfl_xor_sync(0xffffffffu, pr0, 1);
            pr0 += __shfl_xor_sync(0xffffffffu, pr0, 2);
            pr1 += __shfl_xor_sync(0xffffffffu, pr1, 1);
            pr1 += __shfl_xor_sync(0xffffffffu, pr1, 2);
            if (t == 0) {
                int r = wr * 32 + mi * 16 + g;
                atomicAdd(&sCW[r], pr0);
                atomicAdd(&sCW[r + 8], pr1);
            }
        }
        __syncthreads();   // (5) sCW complete, sA reads done

        if (tid < 128) {
            int s = sSrc[tid], d = sDst[tid];
            float dx = coord[s * 3 + 0] - coord[d * 3 + 0];
            float dy = coord[s * 3 + 1] - coord[d * 3 + 1];
            float dz = coord[s * 3 + 2] - coord[d * 3 + 2];
            float r  = dx * dx + dy * dy + dz * dz;
            float inv = 1.0f / (sqrtf(r + 1e-6f) + 1e-6f);
            float cws = sCW[tid] * inv;
            atomicAdd(&g_xsum[d * 3 + 0], cws * dx);
            atomicAdd(&g_xsum[d * 3 + 1], cws * dy);
            atomicAdd(&g_xsum[d * 3 + 2], cws * dz);
        }
        // loop; sync (1) separates these reads from next-tile writes
    }
}

// ---------------- k_node1: t1 = silu([nf|h_neigh] @ W3 + b3) -> g_t1 ----------------
__global__ void __launch_bounds__(512, 1)
k_node1(const float* __restrict__ nf, const float* __restrict__ W3,
        const float* __restrict__ b3) {
    extern __shared__ float sm[];
    float* sWa = sm;                       // 16384 (paired)
    float* sWb = sWa + 16384;              // 16384 (paired)
    float* sA  = sWb + 16384;              // 128*132

    const int tid = threadIdx.x, lane = tid & 31, wid = tid >> 5;
    const int wr = wid & 3, wc = wid >> 2;
    const int g = lane >> 2, t = lane & 3;

    load_paired(sWa, W3, tid, 512);
    load_paired(sWb, W3 + 16384, tid, 512);
    __syncthreads();

    float blo[4], bhi[4];
    {
        int cb = wc * 32 + 2 * t;
#pragma unroll
        for (int ni = 0; ni < 4; ++ni) {
            blo[ni] = __ldg(&b3[cb + ni * 8]);
            bhi[ni] = __ldg(&b3[cb + ni * 8 + 1]);
        }
    }

    const int ntiles = (NN + 127) / 128;
    for (int tile = blockIdx.x; tile < ntiles; tile += gridDim.x) {
        const int bn = tile * 128;
        for (int i = tid; i < 4096; i += 512) {
            int row = i >> 5, c4 = (i & 31) * 4;
            int n = bn + row;
            float4 v = make_float4(0.f, 0.f, 0.f, 0.f);
            if (n < NN) v = *(const float4*)&nf[(size_t)n * 128 + c4];
            float* p = &sA[row * 132 + c4];
            p[0] = tf32f(v.x); p[1] = tf32f(v.y); p[2] = tf32f(v.z); p[3] = tf32f(v.w);
        }
        __syncthreads();

        float acc[2][4][4];
#pragma unroll
        for (int mi = 0; mi < 2; ++mi)
#pragma unroll
            for (int ni = 0; ni < 4; ++ni) {
                acc[mi][ni][0] = blo[ni]; acc[mi][ni][1] = bhi[ni];
                acc[mi][ni][2] = blo[ni]; acc[mi][ni][3] = bhi[ni];
            }
        gemm_rApB<132, false, 4>(sA, sWa, 16, acc, wr, wc, lane);
        __syncthreads();
        for (int i = tid; i < 4096; i += 512) {
            int row = i >> 5, c4 = (i & 31) * 4;
            int n = bn + row;
            float4 v = make_float4(0.f, 0.f, 0.f, 0.f);
            if (n < NN) v = *(const float4*)&g_hneigh[(size_t)n * 128 + c4];
            float* p = &sA[row * 132 + c4];
            p[0] = tf32f(v.x); p[1] = tf32f(v.y); p[2] = tf32f(v.z); p[3] = tf32f(v.w);
        }
        __syncthreads();
        gemm_rApB<132, false, 4>(sA, sWb, 16, acc, wr, wc, lane);

#pragma unroll
        for (int mi = 0; mi < 2; ++mi) {
            int r = bn + wr * 32 + mi * 16 + g;
#pragma unroll
            for (int ni = 0; ni < 4; ++ni) {
                int c = wc * 32 + ni * 8 + 2 * t;
                if (r < NN)
                    *(float2*)&g_t1[(size_t)r * 128 + c] =
                        make_float2(tf32f(silu_f(acc[mi][ni][0])), tf32f(silu_f(acc[mi][ni][1])));
                if (r + 8 < NN)
                    *(float2*)&g_t1[(size_t)(r + 8) * 128 + c] =
                        make_float2(tf32f(silu_f(acc[mi][ni][2])), tf32f(silu_f(acc[mi][ni][3])));
            }
        }
        __syncthreads();
    }
}

// ---------------- k_node2: h = t1 @ W4 + b4 -> out ----------------
__global__ void __launch_bounds__(512, 1)
k_node2(const float* __restrict__ W4, const float* __restrict__ b4,
        float* __restrict__ outh) {
    extern __shared__ float sm[];
    float* sW = sm;                        // 16384 (paired)
    float* sA = sW + 16384;                // 128*132

    const int tid = threadIdx.x, lane = tid & 31, wid = tid >> 5;
    const int wr = wid & 3, wc = wid >> 2;
    const int g = lane >> 2, t = lane & 3;

    load_paired(sW, W4, tid, 512);
    __syncthreads();

    float blo[4], bhi[4];
    {
        int cb = wc * 32 + 2 * t;
#pragma unroll
        for (int ni = 0; ni < 4; ++ni) {
            blo[ni] = __ldg(&b4[cb + ni * 8]);
            bhi[ni] = __ldg(&b4[cb + ni * 8 + 1]);
        }
    }

    const int ntiles = (NN + 127) / 128;
    for (int tile = blockIdx.x; tile < ntiles; tile += gridDim.x) {
        const int bn = tile * 128;
        for (int i = tid; i < 4096; i += 512) {
            int row = i >> 5, c4 = (i & 31) * 4;
            int n = bn + row;
            float4 v = make_float4(0.f, 0.f, 0.f, 0.f);
            if (n < NN) v = *(const float4*)&g_t1[(size_t)n * 128 + c4];
            *(float4*)&sA[row * 132 + c4] = v;
        }
        __syncthreads();

        float acc[2][4][4];
#pragma unroll
        for (int mi = 0; mi < 2; ++mi)
#pragma unroll
            for (int ni = 0; ni < 4; ++ni) {
                acc[mi][ni][0] = blo[ni]; acc[mi][ni][1] = bhi[ni];
                acc[mi][ni][2] = blo[ni]; acc[mi][ni][3] = bhi[ni];
            }
        gemm_rApB<132, false, 4>(sA, sW, 16, acc, wr, wc, lane);

#pragma unroll
        for (int mi = 0; mi < 2; ++mi) {
            int r = bn + wr * 32 + mi * 16 + g;
#pragma unroll
            for (int ni = 0; ni < 4; ++ni) {
                int c = wc * 32 + ni * 8 + 2 * t;
                if (r < NN)
                    *(float2*)&outh[(size_t)r * 128 + c] =
                        make_float2(acc[mi][ni][0], acc[mi][ni][1]);
                if (r + 8 < NN)
                    *(float2*)&outh[(size_t)(r + 8) * 128 + c] =
                        make_float2(acc[mi][ni][2], acc[mi][ni][3]);
            }
        }
        __syncthreads();
    }
}

// ---------------- k_x / k_fin / k_norm ----------------
__global__ void k_x(const float* __restrict__ coord, float* __restrict__ outx) {
    __shared__ float sred[6];
    int tid = threadIdx.x;
    if (tid < 6) sred[tid] = 0.f;
    __syncthreads();
    float ls[6] = {0.f, 0.f, 0.f, 0.f, 0.f, 0.f};
    int stride = gridDim.x * blockDim.x;
    for (int n = blockIdx.x * blockDim.x + tid; n < NN; n += stride) {
        float deg = fmaxf(g_deg[n], 1.0f);
        float invd = 1.0f / deg;
#pragma unroll
        for (int d = 0; d < 3; ++d) {
            float x = coord[n * 3 + d] + g_xsum[n * 3 + d] * invd;
            outx[n * 3 + d] = x;
            ls[d] += x;
            ls[3 + d] += x * x;
        }
    }
#pragma unroll
    for (int k = 0; k < 6; ++k) atomicAdd(&sred[k], ls[k]);
    __syncthreads();
    if (tid < 6) atomicAdd(&g_red[tid], sred[tid]);
}

__global__ void k_fin() {
    int t = threadIdx.x;
    if (t < 3) {
        float mean = g_red[t] / (float)NN;
        float m2   = g_red[3 + t] / (float)NN;
        float var  = m2 - mean * mean;
        g_red[8 + t]  = mean;
        g_red[11 + t] = 1.0f / (sqrtf(var + 1e-6f) + 1e-6f);
    }
}

__global__ void k_norm(float* __restrict__ outx) {
    int stride = gridDim.x * blockDim.x;
    for (int i = blockIdx.x * blockDim.x + threadIdx.x; i < NN * 3; i += stride) {
        int d = i % 3;
        outx[i] = (outx[i] - g_red[8 + d]) * g_red[11 + d];
    }
}

// ---------------- launch ----------------
extern "C" void kernel_launch(void* const* d_in, const int* in_sizes, int n_in,
                              void* d_out, int out_size) {
    const float* nf    = (const float*)d_in[0];
    const float* coord = (const float*)d_in[1];
    const int*   src   = (const int*)d_in[2];
    const int*   dst   = (const int*)d_in[3];
    const float* W1 = (const float*)d_in[4];
    const float* b1 = (const float*)d_in[5];
    const float* W2 = (const float*)d_in[6];
    const float* b2 = (const float*)d_in[7];
    const float* W3 = (const float*)d_in[8];
    const float* b3 = (const float*)d_in[9];
    const float* W4 = (const float*)d_in[10];
    const float* b4 = (const float*)d_in[11];
    const float* W5 = (const float*)d_in[12];
    const float* b5 = (const float*)d_in[13];
    const float* W6 = (const float*)d_in[14];

    float* outh = (float*)d_out;
    float* outx = outh + (size_t)NN * C;

    const int SM_NPRE = (16384 * 2 + 16896) * 4;
    const int SM_EDGE = (16384 * 2 + 16896 + 128 * 4) * 4 + 2 * 128 * 4;
    const int SM_N1   = (16384 * 2 + 16896) * 4;
    const int SM_N2   = (16384 + 16896) * 4;

    cudaFuncSetAttribute(k_npre,  cudaFuncAttributeMaxDynamicSharedMemorySize, SM_NPRE);
    cudaFuncSetAttribute(k_edge,  cudaFuncAttributeMaxDynamicSharedMemorySize, SM_EDGE);
    cudaFuncSetAttribute(k_node1, cudaFuncAttributeMaxDynamicSharedMemorySize, SM_N1);
    cudaFuncSetAttribute(k_node2, cudaFuncAttributeMaxDynamicSharedMemorySize, SM_N2);

    k_init<<<2048, 256>>>();
    k_npre<<<148, 512, SM_NPRE>>>(nf, W1);
    k_edge<<<148, 512, SM_EDGE>>>(coord, src, dst, W1, b1, W2, b2, W5, b5, W6);
    k_node1<<<148, 512, SM_N1>>>(nf, W3, b3);
    k_node2<<<148, 512, SM_N2>>>(W4, b4, outh);
    k_x<<<160, 256>>>(coord, outx);
    k_fin<<<1, 32>>>();
    k_norm<<<160, 256>>>(outx);
}

// round 10
// speedup vs baseline: 7.4431x; 1.1672x over previous
#include <cuda_runtime.h>
#include <cuda_bf16.h>
#include <math.h>

#define NN 50000
#define NE 800000
#define C  128

// ---------------- device scratch ----------------
static __device__ float g_P1[(size_t)NN * C];    // nf @ W1a
static __device__ float g_P2[(size_t)NN * C];    // nf @ W1b
static __device__ float g_t1[(size_t)NN * C];    // node hidden
static __device__ float g_hneigh[(size_t)NN * C];
static __device__ float g_xsum[NN * 3];
static __device__ float g_deg[NN];
static __device__ float g_red[16];

__device__ __forceinline__ float silu_f(float v) {
    return v / (1.0f + __expf(-v));
}
__device__ __forceinline__ float tf32f(float x) {
    unsigned u;
    asm("cvt.rna.tf32.f32 %0, %1;" : "=r"(u) : "f"(x));
    return __uint_as_float(u);
}
__device__ __forceinline__ unsigned fu(float x) { return __float_as_uint(x); }

__device__ __forceinline__ void mma8(float* d, const unsigned* a, unsigned b0, unsigned b1) {
    asm volatile(
        "mma.sync.aligned.m16n8k8.row.col.f32.tf32.tf32.f32 "
        "{%0,%1,%2,%3}, {%4,%5,%6,%7}, {%8,%9}, {%0,%1,%2,%3};"
        : "+f"(d[0]), "+f"(d[1]), "+f"(d[2]), "+f"(d[3])
        : "r"(a[0]), "r"(a[1]), "r"(a[2]), "r"(a[3]), "r"(b0), "r"(b1));
}

#define GBAR(gr) asm volatile("bar.sync %0, 128;" :: "r"((gr) + 1) : "memory")

// =============== paired-k W layout ===============
// sWp[(kc*128 + c)*8 + 2*(k&3) + ((k>>2)&1)] holds W[k][c], kc = k>>3.
// B-fragment (k=t, k=t+4) for col c is one aligned float2.

// Warp-tile GEMM: A row-major in smem (optional tf32 cvt), B paired.
// Warp computes 32 rows x NI*8 cols (col base wc*NI*8), starting row wr*32.
template<int SA, bool CVTA, int NI>
__device__ __forceinline__ void gemm_rApB(const float* __restrict__ sA,
                                          const float* __restrict__ sWp,
                                          int kchunks, float (&acc)[2][NI][4],
                                          int wr, int wc, int lane) {
    const int g = lane >> 2, t = lane & 3;
    const float* ar = sA + (wr * 32 + g) * SA + t;
    const float* bb = sWp + (wc * (NI * 8) + g) * 8 + 2 * t;
#pragma unroll 4
    for (int kc = 0; kc < kchunks; ++kc) {
        const float* ap = ar + kc * 8;
        float a00 = ap[0],       a01 = ap[8 * SA],       a02 = ap[4],       a03 = ap[8 * SA + 4];
        float a10 = ap[16 * SA], a11 = ap[24 * SA],      a12 = ap[16 * SA + 4], a13 = ap[24 * SA + 4];
        if (CVTA) {
            a00 = tf32f(a00); a01 = tf32f(a01); a02 = tf32f(a02); a03 = tf32f(a03);
            a10 = tf32f(a10); a11 = tf32f(a11); a12 = tf32f(a12); a13 = tf32f(a13);
        }
        unsigned A0[4] = {fu(a00), fu(a01), fu(a02), fu(a03)};
        unsigned A1[4] = {fu(a10), fu(a11), fu(a12), fu(a13)};
        const float* bp = bb + kc * 1024;
#pragma unroll
        for (int ni = 0; ni < NI; ++ni) {
            float2 b = *(const float2*)(bp + ni * 64);
            mma8(acc[0][ni], A0, fu(b.x), fu(b.y));
            mma8(acc[1][ni], A1, fu(b.x), fu(b.y));
        }
    }
}

// load W[16384] (row-major [128][128]) into paired layout with tf32 rounding
__device__ __forceinline__ void load_paired(float* sWp, const float* W, int tid, int nthr) {
    for (int i = tid; i < 16384; i += nthr) {
        int k = i >> 7, c = i & 127;
        int pos = ((k >> 3) * 128 + c) * 8 + 2 * (k & 3) + ((k >> 2) & 1);
        sWp[pos] = tf32f(W[i]);
    }
}

// ---------------- k_init ----------------
__global__ void k_init() {
    const long NC = (long)NN * C, N3 = NN * 3;
    const long TOT = NC + N3 + NN + 16;
    long stride = (long)gridDim.x * blockDim.x;
    for (long i = (long)blockIdx.x * blockDim.x + threadIdx.x; i < TOT; i += stride) {
        if (i < NC) g_hneigh[i] = 0.f;
        else if (i < NC + N3) g_xsum[i - NC] = 0.f;
        else if (i < NC + N3 + NN) g_deg[i - NC - N3] = 0.f;
        else g_red[i - NC - N3 - NN] = 0.f;
    }
}

// ---------------- k_npre: P1 = nf@W1a, P2 = nf@W1b ----------------
__global__ void __launch_bounds__(512, 1)
k_npre(const float* __restrict__ nf, const float* __restrict__ W1) {
    extern __shared__ float sm[];
    float* sWa = sm;                       // 16384 (paired)
    float* sWb = sWa + 16384;              // 16384 (paired)
    float* sA  = sWb + 16384;              // 128*132 = 16896

    const int tid = threadIdx.x, lane = tid & 31, wid = tid >> 5;
    const int wr = wid & 3, wc = wid >> 2;
    const int g = lane >> 2, t = lane & 3;

    load_paired(sWa, W1, tid, 512);
    load_paired(sWb, W1 + 16384, tid, 512);
    __syncthreads();

    const int ntiles = (NN + 127) / 128;
    for (int tile = blockIdx.x; tile < ntiles; tile += gridDim.x) {
        const int bn = tile * 128;
        for (int i = tid; i < 4096; i += 512) {
            int row = i >> 5, c4 = (i & 31) * 4;
            int n = bn + row;
            float4 v = make_float4(0.f, 0.f, 0.f, 0.f);
            if (n < NN) v = *(const float4*)&nf[(size_t)n * 128 + c4];
            float* p = &sA[row * 132 + c4];
            p[0] = tf32f(v.x); p[1] = tf32f(v.y); p[2] = tf32f(v.z); p[3] = tf32f(v.w);
        }
        __syncthreads();

        float acc[2][4][4];
#pragma unroll
        for (int mi = 0; mi < 2; ++mi)
#pragma unroll
            for (int ni = 0; ni < 4; ++ni)
#pragma unroll
                for (int q = 0; q < 4; ++q) acc[mi][ni][q] = 0.f;
        gemm_rApB<132, false, 4>(sA, sWa, 16, acc, wr, wc, lane);
#pragma unroll
        for (int mi = 0; mi < 2; ++mi) {
            int r = bn + wr * 32 + mi * 16 + g;
#pragma unroll
            for (int ni = 0; ni < 4; ++ni) {
                int c = wc * 32 + ni * 8 + 2 * t;
                if (r < NN)
                    *(float2*)&g_P1[(size_t)r * 128 + c] = make_float2(acc[mi][ni][0], acc[mi][ni][1]);
                if (r + 8 < NN)
                    *(float2*)&g_P1[(size_t)(r + 8) * 128 + c] = make_float2(acc[mi][ni][2], acc[mi][ni][3]);
            }
        }
#pragma unroll
        for (int mi = 0; mi < 2; ++mi)
#pragma unroll
            for (int ni = 0; ni < 4; ++ni)
#pragma unroll
                for (int q = 0; q < 4; ++q) acc[mi][ni][q] = 0.f;
        gemm_rApB<132, false, 4>(sA, sWb, 16, acc, wr, wc, lane);
#pragma unroll
        for (int mi = 0; mi < 2; ++mi) {
            int r = bn + wr * 32 + mi * 16 + g;
#pragma unroll
            for (int ni = 0; ni < 4; ++ni) {
                int c = wc * 32 + ni * 8 + 2 * t;
                if (r < NN)
                    *(float2*)&g_P2[(size_t)r * 128 + c] = make_float2(acc[mi][ni][0], acc[mi][ni][1]);
                if (r + 8 < NN)
                    *(float2*)&g_P2[(size_t)(r + 8) * 128 + c] = make_float2(acc[mi][ni][2], acc[mi][ni][3]);
            }
        }
        __syncthreads();
    }
}

// ---------------- k_edge: 4 independent 128-thread groups ----------------
// Group gr (warps wid>>2 == gr, one warp per SMSP) processes 32-edge chunks:
//   h1 = silu(P1[s]+P2[d]+r*wr+b1); h2 = silu(h1@W2+b2) -> scatter;
//   cw = silu(h2@W5+b5).W6 -> coord scatter.
__global__ void __launch_bounds__(512, 1)
k_edge(const float* __restrict__ coord,
       const int* __restrict__ src, const int* __restrict__ dst,
       const float* __restrict__ W1, const float* __restrict__ b1,
       const float* __restrict__ W2, const float* __restrict__ b2,
       const float* __restrict__ W5, const float* __restrict__ b5,
       const float* __restrict__ W6) {
    extern __shared__ float sm[];
    float* sW2p = sm;                      // 16384 (paired)
    float* sW5p = sW2p + 16384;            // 16384 (paired)
    float* sAall = sW5p + 16384;           // 4 * 32*132 = 16896
    float* sWr  = sAall + 16896;           // 128
    float* sB1  = sWr + 128;               // 128
    float* sRadA = sB1 + 128;              // 128 (4 x 32)
    float* sCWA  = sRadA + 128;            // 128 (4 x 32)
    int* sSrcA = (int*)(sCWA + 128);       // 128
    int* sDstA = sSrcA + 128;              // 128

    const int tid = threadIdx.x, lane = tid & 31, wid = tid >> 5;
    const int gr = wid >> 2;               // group 0..3 (4 warps across 4 SMSPs)
    const int wc = wid & 3;                // column warp within group
    const int g = lane >> 2, t = lane & 3;
    const int gt = wc * 32 + lane;         // group-local thread 0..127

    float* sA   = sAall + gr * 4224;       // 32*132 per group
    float* sRad = sRadA + gr * 32;
    float* sCW  = sCWA + gr * 32;
    int* sSrc = sSrcA + gr * 32;
    int* sDst = sDstA + gr * 32;

    load_paired(sW2p, W2, tid, 512);
    load_paired(sW5p, W5, tid, 512);
    if (tid < 128) { sWr[tid] = W1[256 * 128 + tid]; sB1[tid] = b1[tid]; }
    __syncthreads();

    float b2lo[4], b2hi[4], b5lo[4], b5hi[4], w6lo[4], w6hi[4];
    {
        int cb = wc * 32 + 2 * t;
#pragma unroll
        for (int ni = 0; ni < 4; ++ni) {
            b2lo[ni] = __ldg(&b2[cb + ni * 8]); b2hi[ni] = __ldg(&b2[cb + ni * 8 + 1]);
            b5lo[ni] = __ldg(&b5[cb + ni * 8]); b5hi[ni] = __ldg(&b5[cb + ni * 8 + 1]);
            w6lo[ni] = __ldg(&W6[cb + ni * 8]); w6hi[ni] = __ldg(&W6[cb + ni * 8 + 1]);
        }
    }

    const int nchunks = NE / 32;           // 25000
    const int gstride = gridDim.x * 4;
    for (int chunk = blockIdx.x * 4 + gr; chunk < nchunks; chunk += gstride) {
        const int be = chunk * 32;
        if (wc == 0) {                     // one warp loads 32 edges
            int e = be + lane;
            int s = src[e], d = dst[e];
            sSrc[lane] = s; sDst[lane] = d; sCW[lane] = 0.f;
            atomicAdd(&g_deg[d], 1.0f);
            float dx = coord[s * 3 + 0] - coord[d * 3 + 0];
            float dy = coord[s * 3 + 1] - coord[d * 3 + 1];
            float dz = coord[s * 3 + 2] - coord[d * 3 + 2];
            sRad[lane] = dx * dx + dy * dy + dz * dz;
        }
        GBAR(gr);                          // (1) idx ready; prior readers done

        // gather-assemble h1 (32 rows x 128 cols) into sA
        for (int i = gt; i < 1024; i += 128) {
            int row = i >> 5, c4 = (i & 31) * 4;
            const float4 p1 = *(const float4*)&g_P1[(size_t)sSrc[row] * 128 + c4];
            const float4 p2 = *(const float4*)&g_P2[(size_t)sDst[row] * 128 + c4];
            const float4 w4 = *(const float4*)&sWr[c4];
            const float4 bb = *(const float4*)&sB1[c4];
            float r = sRad[row];
            float4 o;
            o.x = tf32f(silu_f(p1.x + p2.x + r * w4.x + bb.x));
            o.y = tf32f(silu_f(p1.y + p2.y + r * w4.y + bb.y));
            o.z = tf32f(silu_f(p1.z + p2.z + r * w4.z + bb.z));
            o.w = tf32f(silu_f(p1.w + p2.w + r * w4.w + bb.w));
            *(float4*)&sA[row * 132 + c4] = o;
        }
        GBAR(gr);                          // (2) h1 complete

        // GEMM1: h2pre = h1 @ W2 + b2 (warp owns 32x32 block)
        float acc[2][4][4];
#pragma unroll
        for (int mi = 0; mi < 2; ++mi)
#pragma unroll
            for (int ni = 0; ni < 4; ++ni) {
                acc[mi][ni][0] = b2lo[ni]; acc[mi][ni][1] = b2hi[ni];
                acc[mi][ni][2] = b2lo[ni]; acc[mi][ni][3] = b2hi[ni];
            }
        gemm_rApB<132, false, 4>(sA, sW2p, 16, acc, 0, wc, lane);
        GBAR(gr);                          // (3) h1 reads done

        // write h2 = silu(acc) into sA
#pragma unroll
        for (int mi = 0; mi < 2; ++mi) {
            int r = mi * 16 + g;
#pragma unroll
            for (int ni = 0; ni < 4; ++ni) {
                int c = wc * 32 + ni * 8 + 2 * t;
                *(float2*)&sA[r * 132 + c] =
                    make_float2(silu_f(acc[mi][ni][0]), silu_f(acc[mi][ni][1]));
                *(float2*)&sA[(r + 8) * 132 + c] =
                    make_float2(silu_f(acc[mi][ni][2]), silu_f(acc[mi][ni][3]));
            }
        }
        GBAR(gr);                          // (4) h2 complete

        // GEMM2: h3pre = h2 @ W5 + b5 (cvt A)
        float acc2[2][4][4];
#pragma unroll
        for (int mi = 0; mi < 2; ++mi)
#pragma unroll
            for (int ni = 0; ni < 4; ++ni) {
                acc2[mi][ni][0] = b5lo[ni]; acc2[mi][ni][1] = b5hi[ni];
                acc2[mi][ni][2] = b5lo[ni]; acc2[mi][ni][3] = b5hi[ni];
            }
        gemm_rApB<132, true, 4>(sA, sW5p, 16, acc2, 0, wc, lane);

        // scatter h2 -> g_hneigh (vector reduction atomics)
        for (int i = gt; i < 1024; i += 128) {
            int row = i >> 5, c4 = (i & 31) * 4;
            const float4 v = *(const float4*)&sA[row * 132 + c4];
            float* p = &g_hneigh[(size_t)sDst[row] * 128 + c4];
            asm volatile("red.global.add.v4.f32 [%0], {%1,%2,%3,%4};"
                         :: "l"(p), "f"(v.x), "f"(v.y), "f"(v.z), "f"(v.w) : "memory");
        }

        // cw[row] = sum_c silu(h3pre)*W6[c]
#pragma unroll
        for (int mi = 0; mi < 2; ++mi) {
            float pr0 = 0.f, pr1 = 0.f;
#pragma unroll
            for (int ni = 0; ni < 4; ++ni) {
                pr0 += silu_f(acc2[mi][ni][0]) * w6lo[ni] + silu_f(acc2[mi][ni][1]) * w6hi[ni];
                pr1 += silu_f(acc2[mi][ni][2]) * w6lo[ni] + silu_f(acc2[mi][ni][3]) * w6hi[ni];
            }
            pr0 += __shfl_xor_sync(0xffffffffu, pr0, 1);
            pr0 += __shfl_xor_sync(0xffffffffu, pr0, 2);
            pr1 += __shfl_xor_sync(0xffffffffu, pr1, 1);
            pr1 += __shfl_xor_sync(0xffffffffu, pr1, 2);
            if (t == 0) {
                int r = mi * 16 + g;
                atomicAdd(&sCW[r], pr0);
                atomicAdd(&sCW[r + 8], pr1);
            }
        }
        GBAR(gr);                          // (5) sCW complete, sA reads done

        if (wc == 0) {
            int s = sSrc[lane], d = sDst[lane];
            float dx = coord[s * 3 + 0] - coord[d * 3 + 0];
            float dy = coord[s * 3 + 1] - coord[d * 3 + 1];
            float dz = coord[s * 3 + 2] - coord[d * 3 + 2];
            float r  = dx * dx + dy * dy + dz * dz;
            float inv = 1.0f / (sqrtf(r + 1e-6f) + 1e-6f);
            float cws = sCW[lane] * inv;
            atomicAdd(&g_xsum[d * 3 + 0], cws * dx);
            atomicAdd(&g_xsum[d * 3 + 1], cws * dy);
            atomicAdd(&g_xsum[d * 3 + 2], cws * dz);
        }
        // next chunk's idx phase (wc==0, program order) + GBAR(1) gate reuse
    }
}

// ---------------- k_node1: t1 = silu([nf|h_neigh] @ W3 + b3) -> g_t1 ----------------
__global__ void __launch_bounds__(512, 1)
k_node1(const float* __restrict__ nf, const float* __restrict__ W3,
        const float* __restrict__ b3) {
    extern __shared__ float sm[];
    float* sWa = sm;                       // 16384 (paired)
    float* sWb = sWa + 16384;              // 16384 (paired)
    float* sA  = sWb + 16384;              // 128*132

    const int tid = threadIdx.x, lane = tid & 31, wid = tid >> 5;
    const int wr = wid & 3, wc = wid >> 2;
    const int g = lane >> 2, t = lane & 3;

    load_paired(sWa, W3, tid, 512);
    load_paired(sWb, W3 + 16384, tid, 512);
    __syncthreads();

    float blo[4], bhi[4];
    {
        int cb = wc * 32 + 2 * t;
#pragma unroll
        for (int ni = 0; ni < 4; ++ni) {
            blo[ni] = __ldg(&b3[cb + ni * 8]);
            bhi[ni] = __ldg(&b3[cb + ni * 8 + 1]);
        }
    }

    const int ntiles = (NN + 127) / 128;
    for (int tile = blockIdx.x; tile < ntiles; tile += gridDim.x) {
        const int bn = tile * 128;
        for (int i = tid; i < 4096; i += 512) {
            int row = i >> 5, c4 = (i & 31) * 4;
            int n = bn + row;
            float4 v = make_float4(0.f, 0.f, 0.f, 0.f);
            if (n < NN) v = *(const float4*)&nf[(size_t)n * 128 + c4];
            float* p = &sA[row * 132 + c4];
            p[0] = tf32f(v.x); p[1] = tf32f(v.y); p[2] = tf32f(v.z); p[3] = tf32f(v.w);
        }
        __syncthreads();

        float acc[2][4][4];
#pragma unroll
        for (int mi = 0; mi < 2; ++mi)
#pragma unroll
            for (int ni = 0; ni < 4; ++ni) {
                acc[mi][ni][0] = blo[ni]; acc[mi][ni][1] = bhi[ni];
                acc[mi][ni][2] = blo[ni]; acc[mi][ni][3] = bhi[ni];
            }
        gemm_rApB<132, false, 4>(sA, sWa, 16, acc, wr, wc, lane);
        __syncthreads();
        for (int i = tid; i < 4096; i += 512) {
            int row = i >> 5, c4 = (i & 31) * 4;
            int n = bn + row;
            float4 v = make_float4(0.f, 0.f, 0.f, 0.f);
            if (n < NN) v = *(const float4*)&g_hneigh[(size_t)n * 128 + c4];
            float* p = &sA[row * 132 + c4];
            p[0] = tf32f(v.x); p[1] = tf32f(v.y); p[2] = tf32f(v.z); p[3] = tf32f(v.w);
        }
        __syncthreads();
        gemm_rApB<132, false, 4>(sA, sWb, 16, acc, wr, wc, lane);

#pragma unroll
        for (int mi = 0; mi < 2; ++mi) {
            int r = bn + wr * 32 + mi * 16 + g;
#pragma unroll
            for (int ni = 0; ni < 4; ++ni) {
                int c = wc * 32 + ni * 8 + 2 * t;
                if (r < NN)
                    *(float2*)&g_t1[(size_t)r * 128 + c] =
                        make_float2(tf32f(silu_f(acc[mi][ni][0])), tf32f(silu_f(acc[mi][ni][1])));
                if (r + 8 < NN)
                    *(float2*)&g_t1[(size_t)(r + 8) * 128 + c] =
                        make_float2(tf32f(silu_f(acc[mi][ni][2])), tf32f(silu_f(acc[mi][ni][3])));
            }
        }
        __syncthreads();
    }
}

// ---------------- k_node2: h = t1 @ W4 + b4 -> out ----------------
__global__ void __launch_bounds__(512, 1)
k_node2(const float* __restrict__ W4, const float* __restrict__ b4,
        float* __restrict__ outh) {
    extern __shared__ float sm[];
    float* sW = sm;                        // 16384 (paired)
    float* sA = sW + 16384;                // 128*132

    const int tid = threadIdx.x, lane = tid & 31, wid = tid >> 5;
    const int wr = wid & 3, wc = wid >> 2;
    const int g = lane >> 2, t = lane & 3;

    load_paired(sW, W4, tid, 512);
    __syncthreads();

    float blo[4], bhi[4];
    {
        int cb = wc * 32 + 2 * t;
#pragma unroll
        for (int ni = 0; ni < 4; ++ni) {
            blo[ni] = __ldg(&b4[cb + ni * 8]);
            bhi[ni] = __ldg(&b4[cb + ni * 8 + 1]);
        }
    }

    const int ntiles = (NN + 127) / 128;
    for (int tile = blockIdx.x; tile < ntiles; tile += gridDim.x) {
        const int bn = tile * 128;
        for (int i = tid; i < 4096; i += 512) {
            int row = i >> 5, c4 = (i & 31) * 4;
            int n = bn + row;
            float4 v = make_float4(0.f, 0.f, 0.f, 0.f);
            if (n < NN) v = *(const float4*)&g_t1[(size_t)n * 128 + c4];
            *(float4*)&sA[row * 132 + c4] = v;
        }
        __syncthreads();

        float acc[2][4][4];
#pragma unroll
        for (int mi = 0; mi < 2; ++mi)
#pragma unroll
            for (int ni = 0; ni < 4; ++ni) {
                acc[mi][ni][0] = blo[ni]; acc[mi][ni][1] = bhi[ni];
                acc[mi][ni][2] = blo[ni]; acc[mi][ni][3] = bhi[ni];
            }
        gemm_rApB<132, false, 4>(sA, sW, 16, acc, wr, wc, lane);

#pragma unroll
        for (int mi = 0; mi < 2; ++mi) {
            int r = bn + wr * 32 + mi * 16 + g;
#pragma unroll
            for (int ni = 0; ni < 4; ++ni) {
                int c = wc * 32 + ni * 8 + 2 * t;
                if (r < NN)
                    *(float2*)&outh[(size_t)r * 128 + c] =
                        make_float2(acc[mi][ni][0], acc[mi][ni][1]);
                if (r + 8 < NN)
                    *(float2*)&outh[(size_t)(r + 8) * 128 + c] =
                        make_float2(acc[mi][ni][2], acc[mi][ni][3]);
            }
        }
        __syncthreads();
    }
}

// ---------------- k_x / k_fin / k_norm ----------------
__global__ void k_x(const float* __restrict__ coord, float* __restrict__ outx) {
    __shared__ float sred[6];
    int tid = threadIdx.x;
    if (tid < 6) sred[tid] = 0.f;
    __syncthreads();
    float ls[6] = {0.f, 0.f, 0.f, 0.f, 0.f, 0.f};
    int stride = gridDim.x * blockDim.x;
    for (int n = blockIdx.x * blockDim.x + tid; n < NN; n += stride) {
        float deg = fmaxf(g_deg[n], 1.0f);
        float invd = 1.0f / deg;
#pragma unroll
        for (int d = 0; d < 3; ++d) {
            float x = coord[n * 3 + d] + g_xsum[n * 3 + d] * invd;
            outx[n * 3 + d] = x;
            ls[d] += x;
            ls[3 + d] += x * x;
        }
    }
#pragma unroll
    for (int k = 0; k < 6; ++k) atomicAdd(&sred[k], ls[k]);
    __syncthreads();
    if (tid < 6) atomicAdd(&g_red[tid], sred[tid]);
}

__global__ void k_fin() {
    int t = threadIdx.x;
    if (t < 3) {
        float mean = g_red[t] / (float)NN;
        float m2   = g_red[3 + t] / (float)NN;
        float var  = m2 - mean * mean;
        g_red[8 + t]  = mean;
        g_red[11 + t] = 1.0f / (sqrtf(var + 1e-6f) + 1e-6f);
    }
}

__global__ void k_norm(float* __restrict__ outx) {
    int stride = gridDim.x * blockDim.x;
    for (int i = blockIdx.x * blockDim.x + threadIdx.x; i < NN * 3; i += stride) {
        int d = i % 3;
        outx[i] = (outx[i] - g_red[8 + d]) * g_red[11 + d];
    }
}

// ---------------- launch ----------------
extern "C" void kernel_launch(void* const* d_in, const int* in_sizes, int n_in,
                              void* d_out, int out_size) {
    const float* nf    = (const float*)d_in[0];
    const float* coord = (const float*)d_in[1];
    const int*   src   = (const int*)d_in[2];
    const int*   dst   = (const int*)d_in[3];
    const float* W1 = (const float*)d_in[4];
    const float* b1 = (const float*)d_in[5];
    const float* W2 = (const float*)d_in[6];
    const float* b2 = (const float*)d_in[7];
    const float* W3 = (const float*)d_in[8];
    const float* b3 = (const float*)d_in[9];
    const float* W4 = (const float*)d_in[10];
    const float* b4 = (const float*)d_in[11];
    const float* W5 = (const float*)d_in[12];
    const float* b5 = (const float*)d_in[13];
    const float* W6 = (const float*)d_in[14];

    float* outh = (float*)d_out;
    float* outx = outh + (size_t)NN * C;

    const int SM_NPRE = (16384 * 2 + 16896) * 4;
    const int SM_EDGE = (16384 * 2 + 16896 + 128 * 4) * 4 + 2 * 128 * 4;
    const int SM_N1   = (16384 * 2 + 16896) * 4;
    const int SM_N2   = (16384 + 16896) * 4;

    cudaFuncSetAttribute(k_npre,  cudaFuncAttributeMaxDynamicSharedMemorySize, SM_NPRE);
    cudaFuncSetAttribute(k_edge,  cudaFuncAttributeMaxDynamicSharedMemorySize, SM_EDGE);
    cudaFuncSetAttribute(k_node1, cudaFuncAttributeMaxDynamicSharedMemorySize, SM_N1);
    cudaFuncSetAttribute(k_node2, cudaFuncAttributeMaxDynamicSharedMemorySize, SM_N2);

    k_init<<<2048, 256>>>();
    k_npre<<<148, 512, SM_NPRE>>>(nf, W1);
    k_edge<<<148, 512, SM_EDGE>>>(coord, src, dst, W1, b1, W2, b2, W5, b5, W6);
    k_node1<<<148, 512, SM_N1>>>(nf, W3, b3);
    k_node2<<<148, 512, SM_N2>>>(W4, b4, outh);
    k_x<<<160, 256>>>(coord, outx);
    k_fin<<<1, 32>>>();
    k_norm<<<160, 256>>>(outx);
}